// round 4
// baseline (speedup 1.0000x reference)
#include <cuda_runtime.h>
#include <math.h>
#include <stdint.h>

// ---------------- problem constants ----------------
#define N_TOK 2048
#define T_DIM 512
#define H_DIM 2048
#define V_DIM 32000
#define BETAC 0.1f

// ---------------- GEMM tiling ----------------
#define BM 128
#define BN 128
#define BK 32                       // k per stage (bf16 elems, 64B rows)
#define KTILES (H_DIM / BK)         // 64
#define NSPLIT (V_DIM / BN)         // 250
#define MTILES (N_TOK / BM)         // 16
#define NSTAGE 3

// stage layout (bytes): 4 planes of [128 rows][32 k] bf16 (8KB each)
#define P_AHI 0
#define P_ALO 8192
#define P_BHI 16384
#define P_BLO 24576
#define STAGE_BYTES 32768
#define SMEM_BYTES (NSTAGE * STAGE_BYTES)   // 96KB; reduction reuses stage 0

// ---------------- device scratch ----------------
// pre-split bf16 hi/lo planes (static: ~560MB total, allowed as __device__)
__device__ uint16_t g_Whi[V_DIM * H_DIM];
__device__ uint16_t g_Wlo[V_DIM * H_DIM];
__device__ uint16_t g_rWhi[V_DIM * H_DIM];
__device__ uint16_t g_rWlo[V_DIM * H_DIM];
__device__ uint16_t g_Xhi[N_TOK * H_DIM];
__device__ uint16_t g_Xlo[N_TOK * H_DIM];
__device__ uint16_t g_rXhi[N_TOK * H_DIM];
__device__ uint16_t g_rXlo[N_TOK * H_DIM];

__device__ float g_pmax[NSPLIT * N_TOK];
__device__ float g_psum[NSPLIT * N_TOK];
__device__ int   g_parg[NSPLIT * N_TOK];
__device__ float g_rsum[NSPLIT * N_TOK];
__device__ int   g_chosen[N_TOK];
__device__ float g_toklp[N_TOK];
__device__ float g_kl[N_TOK];

// ---------------- helpers ----------------
__device__ __forceinline__ uint32_t smem_u32(const void* p) {
    return (uint32_t)__cvta_generic_to_shared(p);
}

// two fp32 -> packed bf16x2 hi, and packed bf16x2 of the residuals
__device__ __forceinline__ void cvt_split_pair(float x0, float x1,
                                               uint32_t& h, uint32_t& l) {
    uint32_t hp;
    asm("cvt.rn.bf16x2.f32 %0, %1, %2;" : "=r"(hp) : "f"(x1), "f"(x0));
    const float h0 = __uint_as_float(hp << 16);
    const float h1 = __uint_as_float(hp & 0xFFFF0000u);
    const float r0 = x0 - h0;
    const float r1 = x1 - h1;
    uint32_t lp;
    asm("cvt.rn.bf16x2.f32 %0, %1, %2;" : "=r"(lp) : "f"(r1), "f"(r0));
    h = hp; l = lp;
}

__device__ __forceinline__ void ldsm4(uint32_t* r, uint32_t addr) {
    asm volatile("ldmatrix.sync.aligned.m8n8.x4.shared.b16 {%0,%1,%2,%3}, [%4];"
                 : "=r"(r[0]), "=r"(r[1]), "=r"(r[2]), "=r"(r[3]) : "r"(addr));
}

__device__ __forceinline__ void mma16816(float* c, const uint32_t* a,
                                         const uint32_t* b) {
    asm volatile(
        "mma.sync.aligned.m16n8k16.row.col.f32.bf16.bf16.f32 "
        "{%0,%1,%2,%3}, {%4,%5,%6,%7}, {%8,%9}, {%0,%1,%2,%3};"
        : "+f"(c[0]), "+f"(c[1]), "+f"(c[2]), "+f"(c[3])
        : "r"(a[0]), "r"(a[1]), "r"(a[2]), "r"(a[3]), "r"(b[0]), "r"(b[1]));
}

#define CP16(dst, src)                                                       \
    asm volatile("cp.async.cg.shared.global [%0], [%1], 16;" ::              \
                 "r"(dst), "l"(src) : "memory")
#define CP_COMMIT() asm volatile("cp.async.commit_group;" ::: "memory")
#define CP_WAIT2()  asm volatile("cp.async.wait_group %0;" :: "n"(NSTAGE - 1) : "memory")

// swizzled byte offset within a plane: 64B rows, 16B segs XOR'd so every
// 8-row ldmatrix fetch hits 8 distinct 16B bank groups.
__device__ __forceinline__ int sw_off(int row, int seg) {
    return row * 64 + ((seg ^ ((row >> 1) & 3)) << 4);
}

// ============================================================================
// Pre-split: fp32 -> bf16 hi plane + bf16 residual plane
// ============================================================================
__global__ void split_kernel(const float4* __restrict__ src,
                             uint2* __restrict__ hi, uint2* __restrict__ lo,
                             int n4)
{
    const int i = blockIdx.x * blockDim.x + threadIdx.x;
    if (i >= n4) return;
    const float4 v = src[i];
    uint2 h, l;
    cvt_split_pair(v.x, v.y, h.x, l.x);
    cvt_split_pair(v.z, v.w, h.y, l.y);
    hi[i] = h;
    lo[i] = l;
}

// ============================================================================
// bf16x3 HMMA GEMM (128x128 per CTA, full K), cp.async 3-stage pipeline,
// fused fixed-basis sum-exp and optional max/argmax epilogue.
// ============================================================================
template <bool ARG>
__global__ void __launch_bounds__(256, 2)
gemm_hmma(const uint16_t* __restrict__ Ahi, const uint16_t* __restrict__ Alo,
          const uint16_t* __restrict__ Bhi, const uint16_t* __restrict__ Blo,
          const float* __restrict__ bias)
{
    extern __shared__ __align__(1024) char smem[];
    const int tid  = threadIdx.x;
    const int lane = tid & 31;
    const int w    = tid >> 5;
    const int wm   = w & 1;          // M half (64 rows)
    const int wn   = w >> 1;         // N quarter (32 cols)
    const int m0 = blockIdx.x * BM;
    const int v0 = blockIdx.y * BN;
    const uint32_t sb = smem_u32(smem);

    // ---- cp.async loader mapping: 2 segs/plane/thread ----
    const int s0   = tid << 1;               // 0,2,...,510
    const int row0 = s0 >> 2, seg0 = s0 & 3;
    const int row1 = (s0 + 1) >> 2, seg1 = (s0 + 1) & 3;
    const size_t ga0 = (size_t)(m0 + row0) * H_DIM + (seg0 << 3);
    const size_t ga1 = (size_t)(m0 + row1) * H_DIM + (seg1 << 3);
    const size_t gb0 = (size_t)(v0 + row0) * H_DIM + (seg0 << 3);
    const size_t gb1 = (size_t)(v0 + row1) * H_DIM + (seg1 << 3);
    const int so0 = sw_off(row0, seg0);
    const int so1 = sw_off(row1, seg1);

    // ---- ldmatrix per-thread base offsets (kk=0; kk=1 is XOR 32) ----
    const int r_in = lane & 7;
    int offA[4], offB[2];
    {
        const int hm = (lane >> 3) & 1, hk = lane >> 4;
#pragma unroll
        for (int mi = 0; mi < 4; mi++)
            offA[mi] = P_AHI + sw_off(wm * 64 + mi * 16 + hm * 8 + r_in, hk);
    }
    {
        const int hkb = (lane >> 3) & 1, hn = lane >> 4;
#pragma unroll
        for (int bi = 0; bi < 2; bi++)
            offB[bi] = P_BHI + sw_off(wn * 32 + bi * 16 + hn * 8 + r_in, hkb);
    }

    float c[4][4][4];
#pragma unroll
    for (int i = 0; i < 4; i++)
#pragma unroll
        for (int j = 0; j < 4; j++)
#pragma unroll
            for (int k = 0; k < 4; k++) c[i][j][k] = 0.f;

    // ---- prologue: fill NSTAGE stages ----
#pragma unroll
    for (int st = 0; st < NSTAGE; st++) {
        const uint32_t d = sb + st * STAGE_BYTES;
        const int k0 = st * BK;
        CP16(d + P_AHI + so0, Ahi + ga0 + k0);
        CP16(d + P_AHI + so1, Ahi + ga1 + k0);
        CP16(d + P_ALO + so0, Alo + ga0 + k0);
        CP16(d + P_ALO + so1, Alo + ga1 + k0);
        CP16(d + P_BHI + so0, Bhi + gb0 + k0);
        CP16(d + P_BHI + so1, Bhi + gb1 + k0);
        CP16(d + P_BLO + so0, Blo + gb0 + k0);
        CP16(d + P_BLO + so1, Blo + gb1 + k0);
        CP_COMMIT();
    }

#pragma unroll 1
    for (int kt = 0; kt < KTILES; kt++) {
        const int st = kt % NSTAGE;
        const uint32_t stOff = st * STAGE_BYTES;
        CP_WAIT2();
        __syncthreads();

        // ---- compute 2 x k16 from this stage ----
#pragma unroll
        for (int kk = 0; kk < 2; kk++) {
            const int kx = kk << 5;
            uint32_t Bh[2][4], Bl[2][4];
#pragma unroll
            for (int bi = 0; bi < 2; bi++) {
                ldsm4(Bh[bi], sb + ((offB[bi] + stOff) ^ kx));
                ldsm4(Bl[bi], sb + ((offB[bi] + 8192 + stOff) ^ kx));
            }
#pragma unroll
            for (int mi = 0; mi < 4; mi++) {
                uint32_t Ah[4], Al[4];
                ldsm4(Ah, sb + ((offA[mi] + stOff) ^ kx));
                ldsm4(Al, sb + ((offA[mi] + 8192 + stOff) ^ kx));
#pragma unroll
                for (int nf = 0; nf < 4; nf++) {
                    const uint32_t* bh = &Bh[nf >> 1][(nf & 1) * 2];
                    const uint32_t* bl = &Bl[nf >> 1][(nf & 1) * 2];
                    mma16816(c[mi][nf], Ah, bh);
                    mma16816(c[mi][nf], Ah, bl);
                    mma16816(c[mi][nf], Al, bh);
                }
            }
        }
        __syncthreads();

        // ---- refill the stage just consumed with tile kt+NSTAGE ----
        if (kt + NSTAGE < KTILES) {
            const uint32_t d = sb + stOff;
            const int k0 = (kt + NSTAGE) * BK;
            CP16(d + P_AHI + so0, Ahi + ga0 + k0);
            CP16(d + P_AHI + so1, Ahi + ga1 + k0);
            CP16(d + P_ALO + so0, Alo + ga0 + k0);
            CP16(d + P_ALO + so1, Alo + ga1 + k0);
            CP16(d + P_BHI + so0, Bhi + gb0 + k0);
            CP16(d + P_BHI + so1, Bhi + gb1 + k0);
            CP16(d + P_BLO + so0, Blo + gb0 + k0);
            CP16(d + P_BLO + so1, Blo + gb1 + k0);
        }
        CP_COMMIT();   // always commit to keep wait_group accounting aligned
    }

    // ---- epilogue: bias + exp-sum (+ max/argmax) ----
    const int g = lane >> 2, t = lane & 3;
    float sm8[8], mx8[8];
    int am8[8];
#pragma unroll
    for (int i = 0; i < 8; i++) { sm8[i] = 0.f; mx8[i] = -INFINITY; am8[i] = 0; }

#pragma unroll
    for (int mi = 0; mi < 4; mi++) {
#pragma unroll
        for (int nf = 0; nf < 4; nf++) {
            const int col0 = wn * 32 + nf * 8 + 2 * t;
            const float b0v = bias[v0 + col0];
            const float b1v = bias[v0 + col0 + 1];
            const float x00 = c[mi][nf][0] + b0v;
            const float x01 = c[mi][nf][1] + b1v;
            const float x10 = c[mi][nf][2] + b0v;
            const float x11 = c[mi][nf][3] + b1v;
            const int sa = mi * 2, sbI = mi * 2 + 1;
            sm8[sa]  += __expf(x00) + __expf(x01);
            sm8[sbI] += __expf(x10) + __expf(x11);
            if (ARG) {
                if (x00 > mx8[sa])  { mx8[sa]  = x00; am8[sa]  = v0 + col0; }
                if (x01 > mx8[sa])  { mx8[sa]  = x01; am8[sa]  = v0 + col0 + 1; }
                if (x10 > mx8[sbI]) { mx8[sbI] = x10; am8[sbI] = v0 + col0; }
                if (x11 > mx8[sbI]) { mx8[sbI] = x11; am8[sbI] = v0 + col0 + 1; }
            }
        }
    }

    // quad reduce (lanes sharing a row differ only in t)
#pragma unroll
    for (int i = 0; i < 8; i++) {
        float s = sm8[i], m = mx8[i];
        int a = am8[i];
#pragma unroll
        for (int off = 1; off <= 2; off <<= 1) {
            s += __shfl_xor_sync(0xFFFFFFFFu, s, off);
            if (ARG) {
                const float om = __shfl_xor_sync(0xFFFFFFFFu, m, off);
                const int   oa = __shfl_xor_sync(0xFFFFFFFFu, a, off);
                if (om > m || (om == m && oa < a)) { m = om; a = oa; }
            }
        }
        sm8[i] = s; mx8[i] = m; am8[i] = a;
    }

    // cross-warp combine over wn quarters (reuse stage-0 smem, mainloop done)
    float* rS = (float*)(smem);                 // [3][128]
    float* rM = rS + 3 * 128;
    int*   rA = (int*)(rM + 3 * 128);
    __syncthreads();
    if (t == 0 && wn != 0) {
#pragma unroll
        for (int mi = 0; mi < 4; mi++)
#pragma unroll
            for (int h = 0; h < 2; h++) {
                const int rowc = wm * 64 + mi * 16 + h * 8 + g;
                const int i = mi * 2 + h;
                rS[(wn - 1) * 128 + rowc] = sm8[i];
                if (ARG) {
                    rM[(wn - 1) * 128 + rowc] = mx8[i];
                    rA[(wn - 1) * 128 + rowc] = am8[i];
                }
            }
    }
    __syncthreads();
    if (t == 0 && wn == 0) {
#pragma unroll
        for (int mi = 0; mi < 4; mi++)
#pragma unroll
            for (int h = 0; h < 2; h++) {
                const int rowc = wm * 64 + mi * 16 + h * 8 + g;
                const int i = mi * 2 + h;
                float s = sm8[i], m = mx8[i];
                int a = am8[i];
#pragma unroll
                for (int q = 0; q < 3; q++) {
                    s += rS[q * 128 + rowc];
                    if (ARG) {
                        const float om = rM[q * 128 + rowc];
                        const int   oa = rA[q * 128 + rowc];
                        if (om > m || (om == m && oa < a)) { m = om; a = oa; }
                    }
                }
                const int o = blockIdx.y * N_TOK + m0 + rowc;
                if (ARG) { g_psum[o] = s; g_pmax[o] = m; g_parg[o] = a; }
                else     { g_rsum[o] = s; }
            }
    }
}

// ============================================================================
__global__ void combine_policy_kernel() {
    const int n = blockIdx.x * blockDim.x + threadIdx.x;
    if (n >= N_TOK) return;
    float m = -INFINITY, s = 0.f;
    int a = 0;
#pragma unroll 5
    for (int sp = 0; sp < NSPLIT; sp++) {
        const float pm = g_pmax[sp * N_TOK + n];
        s += g_psum[sp * N_TOK + n];
        const int pa = g_parg[sp * N_TOK + n];
        if (pm > m) { m = pm; a = pa; }   // ascending splits: strict > keeps first
    }
    g_chosen[n] = a;
    g_toklp[n] = m - logf(s);
}

// ============================================================================
__global__ void ref_token_kernel(const float* __restrict__ refX,
                                 const float* __restrict__ refW,
                                 const float* __restrict__ refBias)
{
    __shared__ float red[128];
    const int n = blockIdx.x;
    const int tid = threadIdx.x;
    const int ch = g_chosen[n];
    const float4* xa = (const float4*)(refX + (size_t)n * H_DIM);
    const float4* wa = (const float4*)(refW + (size_t)ch * H_DIM);
    float s = 0.f;
#pragma unroll
    for (int i = tid; i < H_DIM / 4; i += 128) {
        const float4 a = xa[i], w = wa[i];
        s += a.x * w.x + a.y * w.y + a.z * w.z + a.w * w.w;
    }
    red[tid] = s;
    __syncthreads();
    for (int st = 64; st >= 1; st >>= 1) {
        if (tid < st) red[tid] += red[tid + st];
        __syncthreads();
    }
    if (tid == 0) {
        const float ref_logit = red[0] + refBias[ch];
        float rs = 0.f;
#pragma unroll 5
        for (int sp = 0; sp < NSPLIT; sp++) rs += g_rsum[sp * N_TOK + n];
        const float d = (ref_logit - logf(rs)) - g_toklp[n];
        g_kl[n] = expm1f(d) - d;
    }
}

// ============================================================================
__global__ void finalize_kernel(const float* __restrict__ mask,
                                const float* __restrict__ rewards,
                                float* __restrict__ out)
{
    __shared__ float sl[256];
    __shared__ float sw[256];
    const int tid = threadIdx.x;
    const double r0 = rewards[0], r1 = rewards[1], r2 = rewards[2], r3 = rewards[3];
    const double mean = (r0 + r1 + r2 + r3) * 0.25;
    const double d0 = r0 - mean, d1 = r1 - mean, d2 = r2 - mean, d3 = r3 - mean;
    const double sd = sqrt((d0 * d0 + d1 * d1 + d2 * d2 + d3 * d3) / 3.0) + 1e-4;
    const float adv[4] = {(float)(d0 / sd), (float)(d1 / sd),
                          (float)(d2 / sd), (float)(d3 / sd)};
    float accL = 0.f, accW = 0.f;
    for (int n = tid; n < N_TOK; n += 256) {
        const float mk = mask[n];
        const int b = n / T_DIM;
        accL += (BETAC * g_kl[n] - adv[b]) * mk;
        accW += mk;
    }
    sl[tid] = accL;
    sw[tid] = accW;
    __syncthreads();
    for (int st = 128; st >= 1; st >>= 1) {
        if (tid < st) { sl[tid] += sl[tid + st]; sw[tid] += sw[tid + st]; }
        __syncthreads();
    }
    if (tid == 0) out[0] = sl[0] / fmaxf(sw[0], 1.0f);
}

// ============================================================================
extern "C" void kernel_launch(void* const* d_in, const int* in_sizes, int n_in,
                              void* d_out, int out_size)
{
    const float* X   = (const float*)d_in[0];
    const float* W   = (const float*)d_in[1];
    const float* msk = (const float*)d_in[2];
    const float* rwd = (const float*)d_in[3];
    const float* bs  = (const float*)d_in[4];
    const float* rX  = (const float*)d_in[5];
    const float* rW  = (const float*)d_in[6];
    const float* rbs = (const float*)d_in[7];
    float* out = (float*)d_out;

    // resolve device symbol addresses (host API, capture-safe)
    static uint16_t *pWhi = nullptr, *pWlo, *prWhi, *prWlo, *pXhi, *pXlo, *prXhi, *prXlo;
    if (!pWhi) {
        cudaGetSymbolAddress((void**)&pWhi,  g_Whi);
        cudaGetSymbolAddress((void**)&pWlo,  g_Wlo);
        cudaGetSymbolAddress((void**)&prWhi, g_rWhi);
        cudaGetSymbolAddress((void**)&prWlo, g_rWlo);
        cudaGetSymbolAddress((void**)&pXhi,  g_Xhi);
        cudaGetSymbolAddress((void**)&pXlo,  g_Xlo);
        cudaGetSymbolAddress((void**)&prXhi, g_rXhi);
        cudaGetSymbolAddress((void**)&prXlo, g_rXlo);
        cudaFuncSetAttribute(gemm_hmma<true>,  cudaFuncAttributeMaxDynamicSharedMemorySize, SMEM_BYTES);
        cudaFuncSetAttribute(gemm_hmma<false>, cudaFuncAttributeMaxDynamicSharedMemorySize, SMEM_BYTES);
    }

    // pre-split all operands to bf16 hi/lo planes
    const int w4 = V_DIM * H_DIM / 4, x4 = N_TOK * H_DIM / 4;
    split_kernel<<<(w4 + 255) / 256, 256>>>((const float4*)W,  (uint2*)pWhi,  (uint2*)pWlo,  w4);
    split_kernel<<<(w4 + 255) / 256, 256>>>((const float4*)rW, (uint2*)prWhi, (uint2*)prWlo, w4);
    split_kernel<<<(x4 + 255) / 256, 256>>>((const float4*)X,  (uint2*)pXhi,  (uint2*)pXlo,  x4);
    split_kernel<<<(x4 + 255) / 256, 256>>>((const float4*)rX, (uint2*)prXhi, (uint2*)prXlo, x4);

    dim3 g1(MTILES, NSPLIT);   // x fastest: 16 M-tiles share each weight tile in L2
    gemm_hmma<true ><<<g1, 256, SMEM_BYTES>>>(pXhi, pXlo, pWhi, pWlo, bs);
    gemm_hmma<false><<<g1, 256, SMEM_BYTES>>>(prXhi, prXlo, prWhi, prWlo, rbs);
    combine_policy_kernel<<<N_TOK / 256, 256>>>();
    ref_token_kernel<<<N_TOK, 128>>>(rX, rW, rbs);
    finalize_kernel<<<1, 256>>>(msk, rwd, out);
}

// round 5
// speedup vs baseline: 2.3421x; 2.3421x over previous
#include <cuda_runtime.h>
#include <math.h>
#include <stdint.h>

// ---------------- problem constants ----------------
#define N_TOK 2048
#define T_DIM 512
#define H_DIM 2048
#define V_DIM 32000
#define BETAC 0.1f
#define DELTA 0.002f              // argmax candidate window (>>70 sigma of bf16x1 err)

// ---------------- GEMM tiling ----------------
#define BM 128
#define BN 128
#define BK 32                     // k per stage (bf16 elems, 64B rows)
#define KTILES (H_DIM / BK)       // 64
#define NSPLIT (V_DIM / BN)       // 250
#define NGRP   (V_DIM / 16)       // 2000 16-col groups
#define MTILES (N_TOK / BM)       // 16
#define NSTAGE 4

#define P_A 0
#define P_B 8192
#define STAGE_BYTES 16384
#define SMEM_BYTES (NSTAGE * STAGE_BYTES)   // 64KB/CTA, 2 CTA/SM

#define CAND_CAP (1 << 20)

// ---------------- device scratch ----------------
__device__ uint16_t g_Whi[V_DIM * H_DIM];
__device__ uint16_t g_rWhi[V_DIM * H_DIM];
__device__ uint16_t g_Xhi[N_TOK * H_DIM];
__device__ uint16_t g_rXhi[N_TOK * H_DIM];

__device__ float g_pmax[N_TOK * NGRP];       // [n][group] approx 16-col maxes
__device__ float g_psum[N_TOK * 256];        // [n][split] policy exp-sums
__device__ float g_rsum[N_TOK * 256];        // [n][split] ref exp-sums
__device__ float g_lse[N_TOK];               // policy log-sum-exp
__device__ unsigned long long g_best[N_TOK]; // packed (orderable fp32 | ~col)
__device__ float g_kl[N_TOK];
__device__ int   g_ccount;
__device__ uint32_t g_cand[CAND_CAP];        // packed n<<11 | group

// ---------------- helpers ----------------
__device__ __forceinline__ uint32_t smem_u32(const void* p) {
    return (uint32_t)__cvta_generic_to_shared(p);
}
__device__ __forceinline__ uint32_t cvt2bf(float x0, float x1) {
    uint32_t h;
    asm("cvt.rn.bf16x2.f32 %0, %1, %2;" : "=r"(h) : "f"(x1), "f"(x0));
    return h;
}
__device__ __forceinline__ void ldsm4(uint32_t* r, uint32_t addr) {
    asm volatile("ldmatrix.sync.aligned.m8n8.x4.shared.b16 {%0,%1,%2,%3}, [%4];"
                 : "=r"(r[0]), "=r"(r[1]), "=r"(r[2]), "=r"(r[3]) : "r"(addr));
}
__device__ __forceinline__ void mma16816(float* c, const uint32_t* a,
                                         const uint32_t* b) {
    asm volatile(
        "mma.sync.aligned.m16n8k16.row.col.f32.bf16.bf16.f32 "
        "{%0,%1,%2,%3}, {%4,%5,%6,%7}, {%8,%9}, {%0,%1,%2,%3};"
        : "+f"(c[0]), "+f"(c[1]), "+f"(c[2]), "+f"(c[3])
        : "r"(a[0]), "r"(a[1]), "r"(a[2]), "r"(a[3]), "r"(b[0]), "r"(b[1]));
}
#define CP16(dst, src)                                                       \
    asm volatile("cp.async.cg.shared.global [%0], [%1], 16;" ::              \
                 "r"(dst), "l"(src) : "memory")
#define CP_COMMIT() asm volatile("cp.async.commit_group;" ::: "memory")
#define CP_WAIT()   asm volatile("cp.async.wait_group %0;" :: "n"(NSTAGE - 1) : "memory")

// swizzled byte offset: 64B rows, 16B segs XOR'd -> conflict-free ldmatrix
__device__ __forceinline__ int sw_off(int row, int seg) {
    return row * 64 + ((seg ^ ((row >> 1) & 3)) << 4);
}
__device__ __forceinline__ uint32_t fkey(float f) {   // orderable float bits
    uint32_t u = __float_as_uint(f);
    return (u & 0x80000000u) ? ~u : (u | 0x80000000u);
}

// ============================================================================
__global__ void reset_kernel() { g_ccount = 0; }

// fp32 -> bf16 hi plane only
__global__ void split_hi(const float4* __restrict__ src, uint2* __restrict__ hi,
                         int n4)
{
    const int i = blockIdx.x * blockDim.x + threadIdx.x;
    if (i >= n4) return;
    const float4 v = src[i];
    hi[i] = make_uint2(cvt2bf(v.x, v.y), cvt2bf(v.z, v.w));
}

// ============================================================================
// bf16x1 HMMA GEMM (128x128 per CTA, full K), cp.async 4-stage pipeline.
// Epilogue: exp-sum per split; if ARG, approx max per 16-col group.
// ============================================================================
template <bool ARG>
__global__ void __launch_bounds__(256, 2)
gemm_bf16(const uint16_t* __restrict__ Ahi, const uint16_t* __restrict__ Bhi,
          const float* __restrict__ bias)
{
    extern __shared__ __align__(1024) char smem[];
    const int tid  = threadIdx.x;
    const int lane = tid & 31;
    const int w    = tid >> 5;
    const int wm   = w & 1;          // M half (64 rows)
    const int wn   = w >> 1;         // N quarter (32 cols)
    const int m0 = blockIdx.x * BM;
    const int v0 = blockIdx.y * BN;
    const uint32_t sb = smem_u32(smem);

    // cp.async loader: 512 segs/plane, 2 per thread per plane
    const int s0   = tid << 1;
    const int row0 = s0 >> 2, seg0 = s0 & 3;
    const int row1 = (s0 + 1) >> 2, seg1 = (s0 + 1) & 3;
    const size_t ga0 = (size_t)(m0 + row0) * H_DIM + (seg0 << 3);
    const size_t ga1 = (size_t)(m0 + row1) * H_DIM + (seg1 << 3);
    const size_t gb0 = (size_t)(v0 + row0) * H_DIM + (seg0 << 3);
    const size_t gb1 = (size_t)(v0 + row1) * H_DIM + (seg1 << 3);
    const int so0 = sw_off(row0, seg0);
    const int so1 = sw_off(row1, seg1);

    // ldmatrix base offsets (kk=0; kk=1 is XOR 32)
    const int r_in = lane & 7;
    int offA[4], offB[2];
    {
        const int hm = (lane >> 3) & 1, hk = lane >> 4;
#pragma unroll
        for (int mi = 0; mi < 4; mi++)
            offA[mi] = P_A + sw_off(wm * 64 + mi * 16 + hm * 8 + r_in, hk);
    }
    {
        const int hkb = (lane >> 3) & 1, hn = lane >> 4;
#pragma unroll
        for (int bi = 0; bi < 2; bi++)
            offB[bi] = P_B + sw_off(wn * 32 + bi * 16 + hn * 8 + r_in, hkb);
    }

    float c[4][4][4];
#pragma unroll
    for (int i = 0; i < 4; i++)
#pragma unroll
        for (int j = 0; j < 4; j++)
#pragma unroll
            for (int k = 0; k < 4; k++) c[i][j][k] = 0.f;

    // prologue: fill NSTAGE stages
#pragma unroll
    for (int st = 0; st < NSTAGE; st++) {
        const uint32_t d = sb + st * STAGE_BYTES;
        const int k0 = st * BK;
        CP16(d + P_A + so0, Ahi + ga0 + k0);
        CP16(d + P_A + so1, Ahi + ga1 + k0);
        CP16(d + P_B + so0, Bhi + gb0 + k0);
        CP16(d + P_B + so1, Bhi + gb1 + k0);
        CP_COMMIT();
    }

#pragma unroll 1
    for (int kt = 0; kt < KTILES; kt++) {
        const uint32_t stOff = (kt & (NSTAGE - 1)) * STAGE_BYTES;
        CP_WAIT();
        __syncthreads();

#pragma unroll
        for (int kk = 0; kk < 2; kk++) {
            const int kx = kk << 5;
            uint32_t Bh[2][4];
#pragma unroll
            for (int bi = 0; bi < 2; bi++)
                ldsm4(Bh[bi], sb + ((offB[bi] + stOff) ^ kx));
#pragma unroll
            for (int mi = 0; mi < 4; mi++) {
                uint32_t Ah[4];
                ldsm4(Ah, sb + ((offA[mi] + stOff) ^ kx));
#pragma unroll
                for (int nf = 0; nf < 4; nf++)
                    mma16816(c[mi][nf], Ah, &Bh[nf >> 1][(nf & 1) * 2]);
            }
        }
        __syncthreads();

        if (kt + NSTAGE < KTILES) {
            const uint32_t d = sb + stOff;
            const int k0 = (kt + NSTAGE) * BK;
            CP16(d + P_A + so0, Ahi + ga0 + k0);
            CP16(d + P_A + so1, Ahi + ga1 + k0);
            CP16(d + P_B + so0, Bhi + gb0 + k0);
            CP16(d + P_B + so1, Bhi + gb1 + k0);
        }
        CP_COMMIT();
    }

    // ---- epilogue ----
    const int g = lane >> 2, t = lane & 3;
    float sm8[8], mx16[8][2];
#pragma unroll
    for (int i = 0; i < 8; i++) {
        sm8[i] = 0.f;
        mx16[i][0] = -INFINITY;
        mx16[i][1] = -INFINITY;
    }

#pragma unroll
    for (int mi = 0; mi < 4; mi++) {
#pragma unroll
        for (int nf = 0; nf < 4; nf++) {
            const int col0 = wn * 32 + nf * 8 + 2 * t;
            const float b0v = bias[v0 + col0];
            const float b1v = bias[v0 + col0 + 1];
            const float x00 = c[mi][nf][0] + b0v;
            const float x01 = c[mi][nf][1] + b1v;
            const float x10 = c[mi][nf][2] + b0v;
            const float x11 = c[mi][nf][3] + b1v;
            const int sa = mi * 2, sbI = sa + 1;
            sm8[sa]  += __expf(x00) + __expf(x01);
            sm8[sbI] += __expf(x10) + __expf(x11);
            if (ARG) {
                const int h = nf >> 1;
                mx16[sa][h]  = fmaxf(mx16[sa][h],  fmaxf(x00, x01));
                mx16[sbI][h] = fmaxf(mx16[sbI][h], fmaxf(x10, x11));
            }
        }
    }

    // quad reduce over t
#pragma unroll
    for (int i = 0; i < 8; i++) {
        float s = sm8[i];
        s += __shfl_xor_sync(0xFFFFFFFFu, s, 1);
        s += __shfl_xor_sync(0xFFFFFFFFu, s, 2);
        sm8[i] = s;
        if (ARG) {
#pragma unroll
            for (int h = 0; h < 2; h++) {
                float m = mx16[i][h];
                m = fmaxf(m, __shfl_xor_sync(0xFFFFFFFFu, m, 1));
                m = fmaxf(m, __shfl_xor_sync(0xFFFFFFFFu, m, 2));
                mx16[i][h] = m;
            }
        }
    }

    // group maxes: owner writes directly (16-col groups never cross warps)
    if (ARG && t == 0) {
        const int gb = blockIdx.y * 8 + wn * 2;
#pragma unroll
        for (int mi = 0; mi < 4; mi++)
#pragma unroll
            for (int hr = 0; hr < 2; hr++) {
                const int rowc = wm * 64 + mi * 16 + hr * 8 + g;
                const int i = mi * 2 + hr;
                g_pmax[(size_t)(m0 + rowc) * NGRP + gb]     = mx16[i][0];
                g_pmax[(size_t)(m0 + rowc) * NGRP + gb + 1] = mx16[i][1];
            }
    }

    // sums: cross-warp combine over 4 quarters via smem
    float* rS = (float*)(smem);           // [3][128]
    __syncthreads();
    if (t == 0 && wn != 0) {
#pragma unroll
        for (int mi = 0; mi < 4; mi++)
#pragma unroll
            for (int hr = 0; hr < 2; hr++) {
                const int rowc = wm * 64 + mi * 16 + hr * 8 + g;
                rS[(wn - 1) * 128 + rowc] = sm8[mi * 2 + hr];
            }
    }
    __syncthreads();
    if (t == 0 && wn == 0) {
#pragma unroll
        for (int mi = 0; mi < 4; mi++)
#pragma unroll
            for (int hr = 0; hr < 2; hr++) {
                const int rowc = wm * 64 + mi * 16 + hr * 8 + g;
                float s = sm8[mi * 2 + hr];
#pragma unroll
                for (int q = 0; q < 3; q++) s += rS[q * 128 + rowc];
                if (ARG) g_psum[(size_t)(m0 + rowc) * 256 + blockIdx.y] = s;
                else     g_rsum[(size_t)(m0 + rowc) * 256 + blockIdx.y] = s;
            }
    }
}

// ============================================================================
// Per token (one warp): approx max over groups, lse, init best, emit candidates
// ============================================================================
__global__ void combine_kernel() {
    const int lane = threadIdx.x & 31;
    const int n = blockIdx.x * 8 + (threadIdx.x >> 5);

    float m = -INFINITY;
    for (int g = lane; g < NGRP; g += 32)
        m = fmaxf(m, g_pmax[(size_t)n * NGRP + g]);
#pragma unroll
    for (int off = 16; off >= 1; off >>= 1)
        m = fmaxf(m, __shfl_xor_sync(0xFFFFFFFFu, m, off));

    float s = 0.f;
    for (int sp = lane; sp < NSPLIT; sp += 32)
        s += g_psum[(size_t)n * 256 + sp];
#pragma unroll
    for (int off = 16; off >= 1; off >>= 1)
        s += __shfl_xor_sync(0xFFFFFFFFu, s, off);

    if (lane == 0) {
        g_lse[n] = logf(s);
        g_best[n] = 0ULL;
    }

    const float thr = m - DELTA;
    for (int g = lane; g < NGRP; g += 32) {
        const bool c = g_pmax[(size_t)n * NGRP + g] >= thr;
        const unsigned b = __ballot_sync(0xFFFFFFFFu, c);
        if (b == 0) continue;
        int base = 0;
        if (lane == 0) base = atomicAdd(&g_ccount, __popc(b));
        base = __shfl_sync(0xFFFFFFFFu, base, 0);
        if (c) {
            const int idx = base + __popc(b & ((1u << lane) - 1));
            if (idx < CAND_CAP) g_cand[idx] = ((uint32_t)n << 11) | (uint32_t)g;
        }
    }
}

// ============================================================================
// Exact fp32 recompute of candidate 16-col groups; atomicMax packed result
// ============================================================================
__global__ void fixup_kernel(const float* __restrict__ X,
                             const float* __restrict__ W,
                             const float* __restrict__ bias)
{
    int cnt = g_ccount;
    if (cnt > CAND_CAP) cnt = CAND_CAP;
    const int tid = threadIdx.x;
    const int colo = tid >> 3;     // 0..15
    const int sub  = tid & 7;

    for (int i = blockIdx.x; i < cnt; i += gridDim.x) {
        const uint32_t e = g_cand[i];
        const int n = e >> 11;
        const int g = e & 2047;
        const int vcol = g * 16 + colo;
        const float4* xr = (const float4*)(X + (size_t)n * H_DIM);
        const float4* wr = (const float4*)(W + (size_t)vcol * H_DIM);
        float s = 0.f;
#pragma unroll 8
        for (int j = 0; j < 64; j++) {
            const int idx = j * 8 + sub;
            const float4 a = xr[idx], b = wr[idx];
            s += a.x * b.x + a.y * b.y + a.z * b.z + a.w * b.w;
        }
#pragma unroll
        for (int off = 4; off >= 1; off >>= 1)
            s += __shfl_down_sync(0xFFFFFFFFu, s, off, 8);
        if (sub == 0) {
            const float val = s + bias[vcol];
            const unsigned long long pk =
                ((unsigned long long)fkey(val) << 32) |
                (unsigned long long)(0xFFFFFFFFu - (uint32_t)vcol);
            atomicMax(&g_best[n], pk);
        }
    }
}

// ============================================================================
// Per token: decode best, exact ref dot at chosen, ref lse, KL
// ============================================================================
__global__ void ref_token_kernel(const float* __restrict__ refX,
                                 const float* __restrict__ refW,
                                 const float* __restrict__ refBias)
{
    __shared__ float red[128];
    __shared__ float red2[128];
    const int n = blockIdx.x;
    const int tid = threadIdx.x;

    const unsigned long long p = g_best[n];
    const uint32_t key = (uint32_t)(p >> 32);
    const uint32_t ub = (key & 0x80000000u) ? (key & 0x7FFFFFFFu) : ~key;
    const float best_val = __uint_as_float(ub);
    const int chosen = (int)(0xFFFFFFFFu - (uint32_t)(p & 0xFFFFFFFFu));

    const float4* xa = (const float4*)(refX + (size_t)n * H_DIM);
    const float4* wa = (const float4*)(refW + (size_t)chosen * H_DIM);
    float s = 0.f;
#pragma unroll
    for (int i = tid; i < H_DIM / 4; i += 128) {
        const float4 a = xa[i], w = wa[i];
        s += a.x * w.x + a.y * w.y + a.z * w.z + a.w * w.w;
    }
    red[tid] = s;
    float rs = (tid < 128) ? 0.f : 0.f;
    rs += (tid < NSPLIT) ? g_rsum[(size_t)n * 256 + tid] : 0.f;
    rs += (tid + 128 < NSPLIT) ? g_rsum[(size_t)n * 256 + tid + 128] : 0.f;
    red2[tid] = rs;
    __syncthreads();
    for (int st = 64; st >= 1; st >>= 1) {
        if (tid < st) { red[tid] += red[tid + st]; red2[tid] += red2[tid + st]; }
        __syncthreads();
    }
    if (tid == 0) {
        const float ref_logit = red[0] + refBias[chosen];
        const float tok_lp = best_val - g_lse[n];
        const float d = (ref_logit - logf(red2[0])) - tok_lp;
        g_kl[n] = expm1f(d) - d;
    }
}

// ============================================================================
__global__ void finalize_kernel(const float* __restrict__ mask,
                                const float* __restrict__ rewards,
                                float* __restrict__ out)
{
    __shared__ float sl[256];
    __shared__ float sw[256];
    const int tid = threadIdx.x;
    const double r0 = rewards[0], r1 = rewards[1], r2 = rewards[2], r3 = rewards[3];
    const double mean = (r0 + r1 + r2 + r3) * 0.25;
    const double d0 = r0 - mean, d1 = r1 - mean, d2 = r2 - mean, d3 = r3 - mean;
    const double sd = sqrt((d0 * d0 + d1 * d1 + d2 * d2 + d3 * d3) / 3.0) + 1e-4;
    const float adv[4] = {(float)(d0 / sd), (float)(d1 / sd),
                          (float)(d2 / sd), (float)(d3 / sd)};
    float accL = 0.f, accW = 0.f;
    for (int n = tid; n < N_TOK; n += 256) {
        const float mk = mask[n];
        const int b = n / T_DIM;
        accL += (BETAC * g_kl[n] - adv[b]) * mk;
        accW += mk;
    }
    sl[tid] = accL;
    sw[tid] = accW;
    __syncthreads();
    for (int st = 128; st >= 1; st >>= 1) {
        if (tid < st) { sl[tid] += sl[tid + st]; sw[tid] += sw[tid + st]; }
        __syncthreads();
    }
    if (tid == 0) out[0] = sl[0] / fmaxf(sw[0], 1.0f);
}

// ============================================================================
extern "C" void kernel_launch(void* const* d_in, const int* in_sizes, int n_in,
                              void* d_out, int out_size)
{
    const float* X   = (const float*)d_in[0];
    const float* W   = (const float*)d_in[1];
    const float* msk = (const float*)d_in[2];
    const float* rwd = (const float*)d_in[3];
    const float* bs  = (const float*)d_in[4];
    const float* rX  = (const float*)d_in[5];
    const float* rW  = (const float*)d_in[6];
    const float* rbs = (const float*)d_in[7];
    float* out = (float*)d_out;

    static uint16_t *pWhi = nullptr, *prWhi, *pXhi, *prXhi;
    if (!pWhi) {
        cudaGetSymbolAddress((void**)&pWhi,  g_Whi);
        cudaGetSymbolAddress((void**)&prWhi, g_rWhi);
        cudaGetSymbolAddress((void**)&pXhi,  g_Xhi);
        cudaGetSymbolAddress((void**)&prXhi, g_rXhi);
        cudaFuncSetAttribute(gemm_bf16<true>,  cudaFuncAttributeMaxDynamicSharedMemorySize, SMEM_BYTES);
        cudaFuncSetAttribute(gemm_bf16<false>, cudaFuncAttributeMaxDynamicSharedMemorySize, SMEM_BYTES);
    }

    reset_kernel<<<1, 1>>>();

    const int w4 = V_DIM * H_DIM / 4, x4 = N_TOK * H_DIM / 4;
    split_hi<<<(w4 + 255) / 256, 256>>>((const float4*)W,  (uint2*)pWhi,  w4);
    split_hi<<<(w4 + 255) / 256, 256>>>((const float4*)rW, (uint2*)prWhi, w4);
    split_hi<<<(x4 + 255) / 256, 256>>>((const float4*)X,  (uint2*)pXhi,  x4);
    split_hi<<<(x4 + 255) / 256, 256>>>((const float4*)rX, (uint2*)prXhi, x4);

    dim3 g1(MTILES, NSPLIT);
    gemm_bf16<true ><<<g1, 256, SMEM_BYTES>>>(pXhi,  pWhi,  bs);
    gemm_bf16<false><<<g1, 256, SMEM_BYTES>>>(prXhi, prWhi, rbs);

    combine_kernel<<<N_TOK / 8, 256>>>();
    fixup_kernel<<<1024, 128>>>(X, W, bs);
    ref_token_kernel<<<N_TOK, 128>>>(rX, rW, rbs);
    finalize_kernel<<<1, 256>>>(msk, rwd, out);
}

// round 6
// speedup vs baseline: 2.4764x; 1.0573x over previous
#include <cuda_runtime.h>
#include <math.h>
#include <stdint.h>

// ---------------- problem constants ----------------
#define N_TOK 2048
#define T_DIM 512
#define H_DIM 2048
#define V_DIM 32000
#define BETAC 0.1f
#define DELTA 0.012f              // argmax window: 12 sigma of fp8 logit noise
#define FP8_SCALE 64.0f
#define INV_SCALE (1.0f / 4096.0f)   // 1/(64*64)

// ---------------- GEMM tiling ----------------
#define BM 128
#define BN 128
#define BK 64                     // k per stage (fp8 elems, 64B rows)
#define KTILES (H_DIM / BK)       // 32
#define NSPLIT (V_DIM / BN)       // 250
#define NGRP   (V_DIM / 16)       // 2000
#define MTILES (N_TOK / BM)       // 16
#define NSTAGE 4

#define P_A 0
#define P_B 8192
#define STAGE_BYTES 16384
#define SMEM_BYTES (NSTAGE * STAGE_BYTES)   // 64KB/CTA, 2 CTA/SM

#define CAND_CAP (1 << 20)

// ---------------- device scratch ----------------
__device__ uint8_t g_Wq[V_DIM * H_DIM];
__device__ uint8_t g_rWq[V_DIM * H_DIM];
__device__ uint8_t g_Xq[N_TOK * H_DIM];
__device__ uint8_t g_rXq[N_TOK * H_DIM];

__device__ float g_pmax[N_TOK * NGRP];       // [n][group] approx 16-col maxes
__device__ float g_psum[N_TOK * 256];        // [n][split] policy exp-sums
__device__ float g_rsum[N_TOK * 256];        // [n][split] ref exp-sums
__device__ float g_lse[N_TOK];
__device__ unsigned long long g_best[N_TOK]; // packed (orderable fp32 | ~col)
__device__ float g_kl[N_TOK];
__device__ int   g_ccount;
__device__ uint32_t g_cand[CAND_CAP];        // packed n<<11 | group

// ---------------- helpers ----------------
__device__ __forceinline__ uint32_t smem_u32(const void* p) {
    return (uint32_t)__cvta_generic_to_shared(p);
}
// 4 fp32 -> 4 packed e4m3 (x0 in lowest byte)
__device__ __forceinline__ uint32_t cvt4fp8(float x0, float x1, float x2, float x3) {
    uint16_t a, b;
    asm("cvt.rn.satfinite.e4m3x2.f32 %0, %1, %2;" : "=h"(a) : "f"(x1), "f"(x0));
    asm("cvt.rn.satfinite.e4m3x2.f32 %0, %1, %2;" : "=h"(b) : "f"(x3), "f"(x2));
    return (uint32_t)a | ((uint32_t)b << 16);
}
__device__ __forceinline__ void ldsm4(uint32_t* r, uint32_t addr) {
    asm volatile("ldmatrix.sync.aligned.m8n8.x4.shared.b16 {%0,%1,%2,%3}, [%4];"
                 : "=r"(r[0]), "=r"(r[1]), "=r"(r[2]), "=r"(r[3]) : "r"(addr));
}
__device__ __forceinline__ void qmma(float* c, const uint32_t* a,
                                     const uint32_t* b) {
    asm volatile(
        "mma.sync.aligned.m16n8k32.row.col.f32.e4m3.e4m3.f32 "
        "{%0,%1,%2,%3}, {%4,%5,%6,%7}, {%8,%9}, {%0,%1,%2,%3};"
        : "+f"(c[0]), "+f"(c[1]), "+f"(c[2]), "+f"(c[3])
        : "r"(a[0]), "r"(a[1]), "r"(a[2]), "r"(a[3]), "r"(b[0]), "r"(b[1]));
}
#define CP16(dst, src)                                                       \
    asm volatile("cp.async.cg.shared.global [%0], [%1], 16;" ::              \
                 "r"(dst), "l"(src) : "memory")
#define CP_COMMIT() asm volatile("cp.async.commit_group;" ::: "memory")
#define CP_WAIT()   asm volatile("cp.async.wait_group %0;" :: "n"(NSTAGE - 1) : "memory")

// swizzled byte offset: 64B rows, 16B segs XOR'd -> conflict-free ldmatrix
__device__ __forceinline__ int sw_off(int row, int seg) {
    return row * 64 + ((seg ^ ((row >> 1) & 3)) << 4);
}
__device__ __forceinline__ uint32_t fkey(float f) {   // orderable float bits
    uint32_t u = __float_as_uint(f);
    return (u & 0x80000000u) ? ~u : (u | 0x80000000u);
}

// ============================================================================
__global__ void reset_kernel() { g_ccount = 0; }

// fp32 -> e4m3 (scaled by FP8_SCALE); 4 float4 per thread for MLP
__global__ void split_fp8(const float4* __restrict__ src,
                          uint32_t* __restrict__ dst, int n4)
{
    const int i0 = (blockIdx.x * blockDim.x + threadIdx.x) * 4;
#pragma unroll
    for (int j = 0; j < 4; j++) {
        const int i = i0 + j;
        if (i < n4) {
            const float4 v = src[i];
            dst[i] = cvt4fp8(v.x * FP8_SCALE, v.y * FP8_SCALE,
                             v.z * FP8_SCALE, v.w * FP8_SCALE);
        }
    }
}

// ============================================================================
// e4m3 QMMA GEMM (128x128 per CTA, full K), cp.async 4-stage pipeline.
// Epilogue: exp-sum per split; if ARG, approx max per 16-col group.
// ============================================================================
template <bool ARG>
__global__ void __launch_bounds__(256, 2)
gemm_fp8(const uint8_t* __restrict__ Aq, const uint8_t* __restrict__ Bq,
         const float* __restrict__ bias)
{
    extern __shared__ __align__(1024) char smem[];
    const int tid  = threadIdx.x;
    const int lane = tid & 31;
    const int w    = tid >> 5;
    const int wm   = w & 1;          // M half (64 rows)
    const int wn   = w >> 1;         // N quarter (32 cols)
    const int m0 = blockIdx.x * BM;
    const int v0 = blockIdx.y * BN;
    const uint32_t sb = smem_u32(smem);

    // cp.async loader: 512 segs/plane (128 rows x 4x16B), 2 per thread per plane
    const int s0   = tid << 1;
    const int row0 = s0 >> 2, seg0 = s0 & 3;
    const int row1 = (s0 + 1) >> 2, seg1 = (s0 + 1) & 3;
    const size_t ga0 = (size_t)(m0 + row0) * H_DIM + (seg0 << 4);
    const size_t ga1 = (size_t)(m0 + row1) * H_DIM + (seg1 << 4);
    const size_t gb0 = (size_t)(v0 + row0) * H_DIM + (seg0 << 4);
    const size_t gb1 = (size_t)(v0 + row1) * H_DIM + (seg1 << 4);
    const int so0 = sw_off(row0, seg0);
    const int so1 = sw_off(row1, seg1);

    // ldmatrix base offsets (kk=0; kk=1 is XOR 32)
    const int r_in = lane & 7;
    int offA[4], offB[2];
    {
        const int hm = (lane >> 3) & 1, hk = lane >> 4;
#pragma unroll
        for (int mi = 0; mi < 4; mi++)
            offA[mi] = P_A + sw_off(wm * 64 + mi * 16 + hm * 8 + r_in, hk);
    }
    {
        const int hkb = (lane >> 3) & 1, hn = lane >> 4;
#pragma unroll
        for (int bi = 0; bi < 2; bi++)
            offB[bi] = P_B + sw_off(wn * 32 + bi * 16 + hn * 8 + r_in, hkb);
    }

    float c[4][4][4];
#pragma unroll
    for (int i = 0; i < 4; i++)
#pragma unroll
        for (int j = 0; j < 4; j++)
#pragma unroll
            for (int k = 0; k < 4; k++) c[i][j][k] = 0.f;

    // prologue: fill NSTAGE stages
#pragma unroll
    for (int st = 0; st < NSTAGE; st++) {
        const uint32_t d = sb + st * STAGE_BYTES;
        const int k0 = st * BK;
        CP16(d + P_A + so0, Aq + ga0 + k0);
        CP16(d + P_A + so1, Aq + ga1 + k0);
        CP16(d + P_B + so0, Bq + gb0 + k0);
        CP16(d + P_B + so1, Bq + gb1 + k0);
        CP_COMMIT();
    }

#pragma unroll 1
    for (int kt = 0; kt < KTILES; kt++) {
        const uint32_t stOff = (kt & (NSTAGE - 1)) * STAGE_BYTES;
        CP_WAIT();
        __syncthreads();

#pragma unroll
        for (int kk = 0; kk < 2; kk++) {        // each kk covers k32 (32B)
            const int kx = kk << 5;
            uint32_t Bh[2][4];
#pragma unroll
            for (int bi = 0; bi < 2; bi++)
                ldsm4(Bh[bi], sb + ((offB[bi] + stOff) ^ kx));
#pragma unroll
            for (int mi = 0; mi < 4; mi++) {
                uint32_t Ah[4];
                ldsm4(Ah, sb + ((offA[mi] + stOff) ^ kx));
#pragma unroll
                for (int nf = 0; nf < 4; nf++)
                    qmma(c[mi][nf], Ah, &Bh[nf >> 1][(nf & 1) * 2]);
            }
        }
        __syncthreads();

        if (kt + NSTAGE < KTILES) {
            const uint32_t d = sb + stOff;
            const int k0 = (kt + NSTAGE) * BK;
            CP16(d + P_A + so0, Aq + ga0 + k0);
            CP16(d + P_A + so1, Aq + ga1 + k0);
            CP16(d + P_B + so0, Bq + gb0 + k0);
            CP16(d + P_B + so1, Bq + gb1 + k0);
        }
        CP_COMMIT();
    }

    // ---- epilogue ----
    const int g = lane >> 2, t = lane & 3;
    float sm8[8], mx16[8][2];
#pragma unroll
    for (int i = 0; i < 8; i++) {
        sm8[i] = 0.f;
        mx16[i][0] = -INFINITY;
        mx16[i][1] = -INFINITY;
    }

#pragma unroll
    for (int mi = 0; mi < 4; mi++) {
#pragma unroll
        for (int nf = 0; nf < 4; nf++) {
            const int col0 = wn * 32 + nf * 8 + 2 * t;
            const float b0v = bias[v0 + col0];
            const float b1v = bias[v0 + col0 + 1];
            const float x00 = c[mi][nf][0] * INV_SCALE + b0v;
            const float x01 = c[mi][nf][1] * INV_SCALE + b1v;
            const float x10 = c[mi][nf][2] * INV_SCALE + b0v;
            const float x11 = c[mi][nf][3] * INV_SCALE + b1v;
            const int sa = mi * 2, sbI = sa + 1;
            sm8[sa]  += __expf(x00) + __expf(x01);
            sm8[sbI] += __expf(x10) + __expf(x11);
            if (ARG) {
                const int h = nf >> 1;
                mx16[sa][h]  = fmaxf(mx16[sa][h],  fmaxf(x00, x01));
                mx16[sbI][h] = fmaxf(mx16[sbI][h], fmaxf(x10, x11));
            }
        }
    }

    // quad reduce over t
#pragma unroll
    for (int i = 0; i < 8; i++) {
        float s = sm8[i];
        s += __shfl_xor_sync(0xFFFFFFFFu, s, 1);
        s += __shfl_xor_sync(0xFFFFFFFFu, s, 2);
        sm8[i] = s;
        if (ARG) {
#pragma unroll
            for (int h = 0; h < 2; h++) {
                float m = mx16[i][h];
                m = fmaxf(m, __shfl_xor_sync(0xFFFFFFFFu, m, 1));
                m = fmaxf(m, __shfl_xor_sync(0xFFFFFFFFu, m, 2));
                mx16[i][h] = m;
            }
        }
    }

    if (ARG && t == 0) {
        const int gb = blockIdx.y * 8 + wn * 2;
#pragma unroll
        for (int mi = 0; mi < 4; mi++)
#pragma unroll
            for (int hr = 0; hr < 2; hr++) {
                const int rowc = wm * 64 + mi * 16 + hr * 8 + g;
                const int i = mi * 2 + hr;
                g_pmax[(size_t)(m0 + rowc) * NGRP + gb]     = mx16[i][0];
                g_pmax[(size_t)(m0 + rowc) * NGRP + gb + 1] = mx16[i][1];
            }
    }

    // sums: cross-warp combine over 4 quarters via smem
    float* rS = (float*)(smem);           // [3][128]
    __syncthreads();
    if (t == 0 && wn != 0) {
#pragma unroll
        for (int mi = 0; mi < 4; mi++)
#pragma unroll
            for (int hr = 0; hr < 2; hr++) {
                const int rowc = wm * 64 + mi * 16 + hr * 8 + g;
                rS[(wn - 1) * 128 + rowc] = sm8[mi * 2 + hr];
            }
    }
    __syncthreads();
    if (t == 0 && wn == 0) {
#pragma unroll
        for (int mi = 0; mi < 4; mi++)
#pragma unroll
            for (int hr = 0; hr < 2; hr++) {
                const int rowc = wm * 64 + mi * 16 + hr * 8 + g;
                float s = sm8[mi * 2 + hr];
#pragma unroll
                for (int q = 0; q < 3; q++) s += rS[q * 128 + rowc];
                if (ARG) g_psum[(size_t)(m0 + rowc) * 256 + blockIdx.y] = s;
                else     g_rsum[(size_t)(m0 + rowc) * 256 + blockIdx.y] = s;
            }
    }
}

// ============================================================================
// Per token (one warp): approx max, lse, init best, emit candidate groups
// ============================================================================
__global__ void combine_kernel() {
    const int lane = threadIdx.x & 31;
    const int n = blockIdx.x * 8 + (threadIdx.x >> 5);

    float m = -INFINITY;
    for (int g = lane; g < NGRP; g += 32)
        m = fmaxf(m, g_pmax[(size_t)n * NGRP + g]);
#pragma unroll
    for (int off = 16; off >= 1; off >>= 1)
        m = fmaxf(m, __shfl_xor_sync(0xFFFFFFFFu, m, off));

    float s = 0.f;
    for (int sp = lane; sp < NSPLIT; sp += 32)
        s += g_psum[(size_t)n * 256 + sp];
#pragma unroll
    for (int off = 16; off >= 1; off >>= 1)
        s += __shfl_xor_sync(0xFFFFFFFFu, s, off);

    if (lane == 0) {
        g_lse[n] = logf(s);
        g_best[n] = 0ULL;
    }

    const float thr = m - DELTA;
    for (int g = lane; g < NGRP; g += 32) {
        const bool c = g_pmax[(size_t)n * NGRP + g] >= thr;
        const unsigned b = __ballot_sync(0xFFFFFFFFu, c);
        if (b == 0) continue;
        int base = 0;
        if (lane == 0) base = atomicAdd(&g_ccount, __popc(b));
        base = __shfl_sync(0xFFFFFFFFu, base, 0);
        if (c) {
            const int idx = base + __popc(b & ((1u << lane) - 1));
            if (idx < CAND_CAP) g_cand[idx] = ((uint32_t)n << 11) | (uint32_t)g;
        }
    }
}

// ============================================================================
// Exact fp32 recompute of candidate 16-col groups; atomicMax packed result
// ============================================================================
__global__ void fixup_kernel(const float* __restrict__ X,
                             const float* __restrict__ W,
                             const float* __restrict__ bias)
{
    int cnt = g_ccount;
    if (cnt > CAND_CAP) cnt = CAND_CAP;
    const int tid = threadIdx.x;
    const int colo = tid >> 3;     // 0..15
    const int sub  = tid & 7;

    for (int i = blockIdx.x; i < cnt; i += gridDim.x) {
        const uint32_t e = g_cand[i];
        const int n = e >> 11;
        const int g = e & 2047;
        const int vcol = g * 16 + colo;
        const float4* xr = (const float4*)(X + (size_t)n * H_DIM);
        const float4* wr = (const float4*)(W + (size_t)vcol * H_DIM);
        float s = 0.f;
#pragma unroll 8
        for (int j = 0; j < 64; j++) {
            const int idx = j * 8 + sub;
            const float4 a = xr[idx], b = wr[idx];
            s += a.x * b.x + a.y * b.y + a.z * b.z + a.w * b.w;
        }
#pragma unroll
        for (int off = 4; off >= 1; off >>= 1)
            s += __shfl_down_sync(0xFFFFFFFFu, s, off, 8);
        if (sub == 0) {
            const float val = s + bias[vcol];
            const unsigned long long pk =
                ((unsigned long long)fkey(val) << 32) |
                (unsigned long long)(0xFFFFFFFFu - (uint32_t)vcol);
            atomicMax(&g_best[n], pk);
        }
    }
}

// ============================================================================
// Per token: decode best, exact ref dot at chosen, ref lse, KL
// ============================================================================
__global__ void ref_token_kernel(const float* __restrict__ refX,
                                 const float* __restrict__ refW,
                                 const float* __restrict__ refBias)
{
    __shared__ float red[128];
    __shared__ float red2[128];
    const int n = blockIdx.x;
    const int tid = threadIdx.x;

    const unsigned long long p = g_best[n];
    const uint32_t key = (uint32_t)(p >> 32);
    const uint32_t ub = (key & 0x80000000u) ? (key & 0x7FFFFFFFu) : ~key;
    const float best_val = __uint_as_float(ub);
    const int chosen = (int)(0xFFFFFFFFu - (uint32_t)(p & 0xFFFFFFFFu));

    const float4* xa = (const float4*)(refX + (size_t)n * H_DIM);
    const float4* wa = (const float4*)(refW + (size_t)chosen * H_DIM);
    float s = 0.f;
#pragma unroll
    for (int i = tid; i < H_DIM / 4; i += 128) {
        const float4 a = xa[i], w = wa[i];
        s += a.x * w.x + a.y * w.y + a.z * w.z + a.w * w.w;
    }
    red[tid] = s;
    float rs = 0.f;
    rs += (tid < NSPLIT) ? g_rsum[(size_t)n * 256 + tid] : 0.f;
    rs += (tid + 128 < NSPLIT) ? g_rsum[(size_t)n * 256 + tid + 128] : 0.f;
    red2[tid] = rs;
    __syncthreads();
    for (int st = 64; st >= 1; st >>= 1) {
        if (tid < st) { red[tid] += red[tid + st]; red2[tid] += red2[tid + st]; }
        __syncthreads();
    }
    if (tid == 0) {
        const float ref_logit = red[0] + refBias[chosen];
        const float tok_lp = best_val - g_lse[n];
        const float d = (ref_logit - logf(red2[0])) - tok_lp;
        g_kl[n] = expm1f(d) - d;
    }
}

// ============================================================================
__global__ void finalize_kernel(const float* __restrict__ mask,
                                const float* __restrict__ rewards,
                                float* __restrict__ out)
{
    __shared__ float sl[256];
    __shared__ float sw[256];
    const int tid = threadIdx.x;
    const double r0 = rewards[0], r1 = rewards[1], r2 = rewards[2], r3 = rewards[3];
    const double mean = (r0 + r1 + r2 + r3) * 0.25;
    const double d0 = r0 - mean, d1 = r1 - mean, d2 = r2 - mean, d3 = r3 - mean;
    const double sd = sqrt((d0 * d0 + d1 * d1 + d2 * d2 + d3 * d3) / 3.0) + 1e-4;
    const float adv[4] = {(float)(d0 / sd), (float)(d1 / sd),
                          (float)(d2 / sd), (float)(d3 / sd)};
    float accL = 0.f, accW = 0.f;
    for (int n = tid; n < N_TOK; n += 256) {
        const float mk = mask[n];
        const int b = n / T_DIM;
        accL += (BETAC * g_kl[n] - adv[b]) * mk;
        accW += mk;
    }
    sl[tid] = accL;
    sw[tid] = accW;
    __syncthreads();
    for (int st = 128; st >= 1; st >>= 1) {
        if (tid < st) { sl[tid] += sl[tid + st]; sw[tid] += sw[tid + st]; }
        __syncthreads();
    }
    if (tid == 0) out[0] = sl[0] / fmaxf(sw[0], 1.0f);
}

// ============================================================================
extern "C" void kernel_launch(void* const* d_in, const int* in_sizes, int n_in,
                              void* d_out, int out_size)
{
    const float* X   = (const float*)d_in[0];
    const float* W   = (const float*)d_in[1];
    const float* msk = (const float*)d_in[2];
    const float* rwd = (const float*)d_in[3];
    const float* bs  = (const float*)d_in[4];
    const float* rX  = (const float*)d_in[5];
    const float* rW  = (const float*)d_in[6];
    const float* rbs = (const float*)d_in[7];
    float* out = (float*)d_out;

    static uint8_t *pWq = nullptr, *prWq, *pXq, *prXq;
    if (!pWq) {
        cudaGetSymbolAddress((void**)&pWq,  g_Wq);
        cudaGetSymbolAddress((void**)&prWq, g_rWq);
        cudaGetSymbolAddress((void**)&pXq,  g_Xq);
        cudaGetSymbolAddress((void**)&prXq, g_rXq);
        cudaFuncSetAttribute(gemm_fp8<true>,  cudaFuncAttributeMaxDynamicSharedMemorySize, SMEM_BYTES);
        cudaFuncSetAttribute(gemm_fp8<false>, cudaFuncAttributeMaxDynamicSharedMemorySize, SMEM_BYTES);
    }

    reset_kernel<<<1, 1>>>();

    const int w4 = V_DIM * H_DIM / 4, x4 = N_TOK * H_DIM / 4;
    split_fp8<<<(w4 / 4 + 255) / 256, 256>>>((const float4*)W,  (uint32_t*)pWq,  w4);
    split_fp8<<<(w4 / 4 + 255) / 256, 256>>>((const float4*)rW, (uint32_t*)prWq, w4);
    split_fp8<<<(x4 / 4 + 255) / 256, 256>>>((const float4*)X,  (uint32_t*)pXq,  x4);
    split_fp8<<<(x4 / 4 + 255) / 256, 256>>>((const float4*)rX, (uint32_t*)prXq, x4);

    dim3 g1(MTILES, NSPLIT);
    gemm_fp8<true ><<<g1, 256, SMEM_BYTES>>>(pXq,  pWq,  bs);
    gemm_fp8<false><<<g1, 256, SMEM_BYTES>>>(prXq, prWq, rbs);

    combine_kernel<<<N_TOK / 8, 256>>>();
    fixup_kernel<<<1024, 128>>>(X, W, bs);
    ref_token_kernel<<<N_TOK, 128>>>(rX, rW, rbs);
    finalize_kernel<<<1, 256>>>(msk, rwd, out);
}

// round 7
// speedup vs baseline: 2.4920x; 1.0063x over previous
#include <cuda_runtime.h>
#include <cuda_fp16.h>
#include <math.h>
#include <stdint.h>

// ---------------- problem constants ----------------
#define N_TOK 2048
#define T_DIM 512
#define H_DIM 2048
#define V_DIM 32000
#define BETAC 0.1f
#define DELTA 0.008f              // argmax window: ~17 sigma of fp8+f16acc noise
#define FP8_SCALE 64.0f
#define INV_SCALE (1.0f / 4096.0f)   // 1/(64*64)

// ---------------- GEMM tiling ----------------
#define BM 128
#define BN 128
#define BK 64                     // k per stage (fp8 elems, 64B rows)
#define KTILES (H_DIM / BK)       // 32
#define NSPLIT (V_DIM / BN)       // 250
#define NGRP   (V_DIM / 16)       // 2000
#define MTILES (N_TOK / BM)       // 16
#define NSTAGE 4

#define P_A 0
#define P_B 8192
#define STAGE_BYTES 16384
#define SMEM_BYTES (NSTAGE * STAGE_BYTES)   // 64KB/CTA, 2 CTA/SM

#define CAND_CAP (1 << 20)

// ---------------- device scratch ----------------
__device__ uint8_t g_Wq[V_DIM * H_DIM];
__device__ uint8_t g_rWq[V_DIM * H_DIM];
__device__ uint8_t g_Xq[N_TOK * H_DIM];
__device__ uint8_t g_rXq[N_TOK * H_DIM];

__device__ float g_pmax[N_TOK * NGRP];       // [n][group] approx 16-col maxes
__device__ float g_psum[N_TOK * 256];        // [n][split] policy exp-sums
__device__ float g_rsum[N_TOK * 256];        // [n][split] ref exp-sums
__device__ float g_lse[N_TOK];
__device__ unsigned long long g_best[N_TOK]; // packed (orderable fp32 | ~col)
__device__ float g_kl[N_TOK];
__device__ int   g_ccount;
__device__ uint32_t g_cand[CAND_CAP];        // packed n<<11 | group

// ---------------- helpers ----------------
__device__ __forceinline__ uint32_t smem_u32(const void* p) {
    return (uint32_t)__cvta_generic_to_shared(p);
}
// 4 fp32 -> 4 packed e4m3 (x0 in lowest byte)
__device__ __forceinline__ uint32_t cvt4fp8(float x0, float x1, float x2, float x3) {
    uint16_t a, b;
    asm("cvt.rn.satfinite.e4m3x2.f32 %0, %1, %2;" : "=h"(a) : "f"(x1), "f"(x0));
    asm("cvt.rn.satfinite.e4m3x2.f32 %0, %1, %2;" : "=h"(b) : "f"(x3), "f"(x2));
    return (uint32_t)a | ((uint32_t)b << 16);
}
__device__ __forceinline__ void ldsm4(uint32_t* r, uint32_t addr) {
    asm volatile("ldmatrix.sync.aligned.m8n8.x4.shared.b16 {%0,%1,%2,%3}, [%4];"
                 : "=r"(r[0]), "=r"(r[1]), "=r"(r[2]), "=r"(r[3]) : "r"(addr));
}
// fp8 MMA with f16 accumulators: c[0]={r, c0,c1}, c[1]={r+8, c0,c1}
__device__ __forceinline__ void qmma_f16(uint32_t* c, const uint32_t* a,
                                         const uint32_t* b) {
    asm volatile(
        "mma.sync.aligned.m16n8k32.row.col.f16.e4m3.e4m3.f16 "
        "{%0,%1}, {%2,%3,%4,%5}, {%6,%7}, {%0,%1};"
        : "+r"(c[0]), "+r"(c[1])
        : "r"(a[0]), "r"(a[1]), "r"(a[2]), "r"(a[3]), "r"(b[0]), "r"(b[1]));
}
#define CP16(dst, src)                                                       \
    asm volatile("cp.async.cg.shared.global [%0], [%1], 16;" ::              \
                 "r"(dst), "l"(src) : "memory")
#define CP_COMMIT() asm volatile("cp.async.commit_group;" ::: "memory")
#define CP_WAIT()   asm volatile("cp.async.wait_group %0;" :: "n"(NSTAGE - 1) : "memory")

// swizzled byte offset: 64B rows, 16B segs XOR'd -> conflict-free ldmatrix
__device__ __forceinline__ int sw_off(int row, int seg) {
    return row * 64 + ((seg ^ ((row >> 1) & 3)) << 4);
}
__device__ __forceinline__ uint32_t fkey(float f) {   // orderable float bits
    uint32_t u = __float_as_uint(f);
    return (u & 0x80000000u) ? ~u : (u | 0x80000000u);
}

// ============================================================================
__global__ void reset_kernel() { g_ccount = 0; }

// fp32 -> e4m3 (scaled); grid-stride, 8 independent float4 per iteration
__global__ void split_fp8(const float4* __restrict__ src,
                          uint32_t* __restrict__ dst, int n4)
{
    const int stride = gridDim.x * blockDim.x;
    for (int base = blockIdx.x * blockDim.x + threadIdx.x; base * 8 < n4;
         base += stride) {
        const int i0 = base * 8;
        float4 v[8];
#pragma unroll
        for (int j = 0; j < 8; j++) v[j] = src[i0 + j];   // 8 LDG in flight
#pragma unroll
        for (int j = 0; j < 8; j++)
            dst[i0 + j] = cvt4fp8(v[j].x * FP8_SCALE, v[j].y * FP8_SCALE,
                                  v[j].z * FP8_SCALE, v[j].w * FP8_SCALE);
    }
}

// ============================================================================
// e4m3 QMMA GEMM with f16 accumulators (128x128 per CTA, full K),
// cp.async 4-stage pipeline. Epilogue: exp-sum per split; if ARG, group maxes.
// ============================================================================
template <bool ARG>
__global__ void __launch_bounds__(256, 2)
gemm_fp8(const uint8_t* __restrict__ Aq, const uint8_t* __restrict__ Bq,
         const float* __restrict__ bias)
{
    extern __shared__ __align__(1024) char smem[];
    const int tid  = threadIdx.x;
    const int lane = tid & 31;
    const int w    = tid >> 5;
    const int wm   = w & 1;          // M half (64 rows)
    const int wn   = w >> 1;         // N quarter (32 cols)
    const int m0 = blockIdx.x * BM;
    const int v0 = blockIdx.y * BN;
    const uint32_t sb = smem_u32(smem);

    // cp.async loader: 512 segs/plane (128 rows x 4x16B), 2 per thread per plane
    const int s0   = tid << 1;
    const int row0 = s0 >> 2, seg0 = s0 & 3;
    const int row1 = (s0 + 1) >> 2, seg1 = (s0 + 1) & 3;
    const size_t ga0 = (size_t)(m0 + row0) * H_DIM + (seg0 << 4);
    const size_t ga1 = (size_t)(m0 + row1) * H_DIM + (seg1 << 4);
    const size_t gb0 = (size_t)(v0 + row0) * H_DIM + (seg0 << 4);
    const size_t gb1 = (size_t)(v0 + row1) * H_DIM + (seg1 << 4);
    const int so0 = sw_off(row0, seg0);
    const int so1 = sw_off(row1, seg1);

    // ldmatrix base offsets (kk=0; kk=1 is XOR 32)
    const int r_in = lane & 7;
    int offA[4], offB[2];
    {
        const int hm = (lane >> 3) & 1, hk = lane >> 4;
#pragma unroll
        for (int mi = 0; mi < 4; mi++)
            offA[mi] = P_A + sw_off(wm * 64 + mi * 16 + hm * 8 + r_in, hk);
    }
    {
        const int hkb = (lane >> 3) & 1, hn = lane >> 4;
#pragma unroll
        for (int bi = 0; bi < 2; bi++)
            offB[bi] = P_B + sw_off(wn * 32 + bi * 16 + hn * 8 + r_in, hkb);
    }

    uint32_t c[4][4][2];            // f16x2 accumulators
#pragma unroll
    for (int i = 0; i < 4; i++)
#pragma unroll
        for (int j = 0; j < 4; j++) { c[i][j][0] = 0u; c[i][j][1] = 0u; }

    // prologue: fill NSTAGE stages
#pragma unroll
    for (int st = 0; st < NSTAGE; st++) {
        const uint32_t d = sb + st * STAGE_BYTES;
        const int k0 = st * BK;
        CP16(d + P_A + so0, Aq + ga0 + k0);
        CP16(d + P_A + so1, Aq + ga1 + k0);
        CP16(d + P_B + so0, Bq + gb0 + k0);
        CP16(d + P_B + so1, Bq + gb1 + k0);
        CP_COMMIT();
    }

#pragma unroll 1
    for (int kt = 0; kt < KTILES; kt++) {
        const uint32_t stOff = (kt & (NSTAGE - 1)) * STAGE_BYTES;
        CP_WAIT();
        __syncthreads();

#pragma unroll
        for (int kk = 0; kk < 2; kk++) {        // each kk covers k32 (32B)
            const int kx = kk << 5;
            uint32_t Bh[2][4];
#pragma unroll
            for (int bi = 0; bi < 2; bi++)
                ldsm4(Bh[bi], sb + ((offB[bi] + stOff) ^ kx));
#pragma unroll
            for (int mi = 0; mi < 4; mi++) {
                uint32_t Ah[4];
                ldsm4(Ah, sb + ((offA[mi] + stOff) ^ kx));
#pragma unroll
                for (int nf = 0; nf < 4; nf++)
                    qmma_f16(c[mi][nf], Ah, &Bh[nf >> 1][(nf & 1) * 2]);
            }
        }
        __syncthreads();

        if (kt + NSTAGE < KTILES) {
            const uint32_t d = sb + stOff;
            const int k0 = (kt + NSTAGE) * BK;
            CP16(d + P_A + so0, Aq + ga0 + k0);
            CP16(d + P_A + so1, Aq + ga1 + k0);
            CP16(d + P_B + so0, Bq + gb0 + k0);
            CP16(d + P_B + so1, Bq + gb1 + k0);
        }
        CP_COMMIT();
    }

    // ---- epilogue ----
    const int g = lane >> 2, t = lane & 3;
    float sm8[8], mx16[8][2];
#pragma unroll
    for (int i = 0; i < 8; i++) {
        sm8[i] = 0.f;
        mx16[i][0] = -INFINITY;
        mx16[i][1] = -INFINITY;
    }

#pragma unroll
    for (int mi = 0; mi < 4; mi++) {
#pragma unroll
        for (int nf = 0; nf < 4; nf++) {
            const int col0 = wn * 32 + nf * 8 + 2 * t;
            const float b0v = bias[v0 + col0];
            const float b1v = bias[v0 + col0 + 1];
            const float2 lo = __half22float2(*(const __half2*)&c[mi][nf][0]);
            const float2 hi = __half22float2(*(const __half2*)&c[mi][nf][1]);
            const float x00 = lo.x * INV_SCALE + b0v;
            const float x01 = lo.y * INV_SCALE + b1v;
            const float x10 = hi.x * INV_SCALE + b0v;
            const float x11 = hi.y * INV_SCALE + b1v;
            const int sa = mi * 2, sbI = sa + 1;
            sm8[sa]  += __expf(x00) + __expf(x01);
            sm8[sbI] += __expf(x10) + __expf(x11);
            if (ARG) {
                const int h = nf >> 1;
                mx16[sa][h]  = fmaxf(mx16[sa][h],  fmaxf(x00, x01));
                mx16[sbI][h] = fmaxf(mx16[sbI][h], fmaxf(x10, x11));
            }
        }
    }

    // quad reduce over t
#pragma unroll
    for (int i = 0; i < 8; i++) {
        float s = sm8[i];
        s += __shfl_xor_sync(0xFFFFFFFFu, s, 1);
        s += __shfl_xor_sync(0xFFFFFFFFu, s, 2);
        sm8[i] = s;
        if (ARG) {
#pragma unroll
            for (int h = 0; h < 2; h++) {
                float m = mx16[i][h];
                m = fmaxf(m, __shfl_xor_sync(0xFFFFFFFFu, m, 1));
                m = fmaxf(m, __shfl_xor_sync(0xFFFFFFFFu, m, 2));
                mx16[i][h] = m;
            }
        }
    }

    if (ARG && t == 0) {
        const int gb = blockIdx.y * 8 + wn * 2;
#pragma unroll
        for (int mi = 0; mi < 4; mi++)
#pragma unroll
            for (int hr = 0; hr < 2; hr++) {
                const int rowc = wm * 64 + mi * 16 + hr * 8 + g;
                const int i = mi * 2 + hr;
                g_pmax[(size_t)(m0 + rowc) * NGRP + gb]     = mx16[i][0];
                g_pmax[(size_t)(m0 + rowc) * NGRP + gb + 1] = mx16[i][1];
            }
    }

    // sums: cross-warp combine over 4 quarters via smem
    float* rS = (float*)(smem);           // [3][128]
    __syncthreads();
    if (t == 0 && wn != 0) {
#pragma unroll
        for (int mi = 0; mi < 4; mi++)
#pragma unroll
            for (int hr = 0; hr < 2; hr++) {
                const int rowc = wm * 64 + mi * 16 + hr * 8 + g;
                rS[(wn - 1) * 128 + rowc] = sm8[mi * 2 + hr];
            }
    }
    __syncthreads();
    if (t == 0 && wn == 0) {
#pragma unroll
        for (int mi = 0; mi < 4; mi++)
#pragma unroll
            for (int hr = 0; hr < 2; hr++) {
                const int rowc = wm * 64 + mi * 16 + hr * 8 + g;
                float s = sm8[mi * 2 + hr];
#pragma unroll
                for (int q = 0; q < 3; q++) s += rS[q * 128 + rowc];
                if (ARG) g_psum[(size_t)(m0 + rowc) * 256 + blockIdx.y] = s;
                else     g_rsum[(size_t)(m0 + rowc) * 256 + blockIdx.y] = s;
            }
    }
}

// ============================================================================
// Per token (one warp): approx max, lse, init best, emit candidate groups
// ============================================================================
__global__ void combine_kernel() {
    const int lane = threadIdx.x & 31;
    const int n = blockIdx.x * 8 + (threadIdx.x >> 5);

    float m = -INFINITY;
    for (int g = lane; g < NGRP; g += 32)
        m = fmaxf(m, g_pmax[(size_t)n * NGRP + g]);
#pragma unroll
    for (int off = 16; off >= 1; off >>= 1)
        m = fmaxf(m, __shfl_xor_sync(0xFFFFFFFFu, m, off));

    float s = 0.f;
    for (int sp = lane; sp < NSPLIT; sp += 32)
        s += g_psum[(size_t)n * 256 + sp];
#pragma unroll
    for (int off = 16; off >= 1; off >>= 1)
        s += __shfl_xor_sync(0xFFFFFFFFu, s, off);

    if (lane == 0) {
        g_lse[n] = logf(s);
        g_best[n] = 0ULL;
    }

    const float thr = m - DELTA;
    for (int g = lane; g < NGRP; g += 32) {
        const bool c = g_pmax[(size_t)n * NGRP + g] >= thr;
        const unsigned b = __ballot_sync(0xFFFFFFFFu, c);
        if (b == 0) continue;
        int base = 0;
        if (lane == 0) base = atomicAdd(&g_ccount, __popc(b));
        base = __shfl_sync(0xFFFFFFFFu, base, 0);
        if (c) {
            const int idx = base + __popc(b & ((1u << lane) - 1));
            if (idx < CAND_CAP) g_cand[idx] = ((uint32_t)n << 11) | (uint32_t)g;
        }
    }
}

// ============================================================================
// Exact fp32 recompute of candidate 16-col groups; atomicMax packed result
// ============================================================================
__global__ void fixup_kernel(const float* __restrict__ X,
                             const float* __restrict__ W,
                             const float* __restrict__ bias)
{
    int cnt = g_ccount;
    if (cnt > CAND_CAP) cnt = CAND_CAP;
    const int tid = threadIdx.x;
    const int colo = tid >> 3;     // 0..15
    const int sub  = tid & 7;

    for (int i = blockIdx.x; i < cnt; i += gridDim.x) {
        const uint32_t e = g_cand[i];
        const int n = e >> 11;
        const int g = e & 2047;
        const int vcol = g * 16 + colo;
        const float4* xr = (const float4*)(X + (size_t)n * H_DIM);
        const float4* wr = (const float4*)(W + (size_t)vcol * H_DIM);
        float s = 0.f;
#pragma unroll 8
        for (int j = 0; j < 64; j++) {
            const int idx = j * 8 + sub;
            const float4 a = xr[idx], b = wr[idx];
            s += a.x * b.x + a.y * b.y + a.z * b.z + a.w * b.w;
        }
#pragma unroll
        for (int off = 4; off >= 1; off >>= 1)
            s += __shfl_down_sync(0xFFFFFFFFu, s, off, 8);
        if (sub == 0) {
            const float val = s + bias[vcol];
            const unsigned long long pk =
                ((unsigned long long)fkey(val) << 32) |
                (unsigned long long)(0xFFFFFFFFu - (uint32_t)vcol);
            atomicMax(&g_best[n], pk);
        }
    }
}

// ============================================================================
// Per token: decode best, exact ref dot at chosen, ref lse, KL
// ============================================================================
__global__ void ref_token_kernel(const float* __restrict__ refX,
                                 const float* __restrict__ refW,
                                 const float* __restrict__ refBias)
{
    __shared__ float red[128];
    __shared__ float red2[128];
    const int n = blockIdx.x;
    const int tid = threadIdx.x;

    const unsigned long long p = g_best[n];
    const uint32_t key = (uint32_t)(p >> 32);
    const uint32_t ub = (key & 0x80000000u) ? (key & 0x7FFFFFFFu) : ~key;
    const float best_val = __uint_as_float(ub);
    const int chosen = (int)(0xFFFFFFFFu - (uint32_t)(p & 0xFFFFFFFFu));

    const float4* xa = (const float4*)(refX + (size_t)n * H_DIM);
    const float4* wa = (const float4*)(refW + (size_t)chosen * H_DIM);
    float s = 0.f;
#pragma unroll
    for (int i = tid; i < H_DIM / 4; i += 128) {
        const float4 a = xa[i], w = wa[i];
        s += a.x * w.x + a.y * w.y + a.z * w.z + a.w * w.w;
    }
    red[tid] = s;
    float rs = 0.f;
    rs += (tid < NSPLIT) ? g_rsum[(size_t)n * 256 + tid] : 0.f;
    rs += (tid + 128 < NSPLIT) ? g_rsum[(size_t)n * 256 + tid + 128] : 0.f;
    red2[tid] = rs;
    __syncthreads();
    for (int st = 64; st >= 1; st >>= 1) {
        if (tid < st) { red[tid] += red[tid + st]; red2[tid] += red2[tid + st]; }
        __syncthreads();
    }
    if (tid == 0) {
        const float ref_logit = red[0] + refBias[chosen];
        const float tok_lp = best_val - g_lse[n];
        const float d = (ref_logit - logf(red2[0])) - tok_lp;
        g_kl[n] = expm1f(d) - d;
    }
}

// ============================================================================
__global__ void finalize_kernel(const float* __restrict__ mask,
                                const float* __restrict__ rewards,
                                float* __restrict__ out)
{
    __shared__ float sl[256];
    __shared__ float sw[256];
    const int tid = threadIdx.x;
    const double r0 = rewards[0], r1 = rewards[1], r2 = rewards[2], r3 = rewards[3];
    const double mean = (r0 + r1 + r2 + r3) * 0.25;
    const double d0 = r0 - mean, d1 = r1 - mean, d2 = r2 - mean, d3 = r3 - mean;
    const double sd = sqrt((d0 * d0 + d1 * d1 + d2 * d2 + d3 * d3) / 3.0) + 1e-4;
    const float adv[4] = {(float)(d0 / sd), (float)(d1 / sd),
                          (float)(d2 / sd), (float)(d3 / sd)};
    float accL = 0.f, accW = 0.f;
    for (int n = tid; n < N_TOK; n += 256) {
        const float mk = mask[n];
        const int b = n / T_DIM;
        accL += (BETAC * g_kl[n] - adv[b]) * mk;
        accW += mk;
    }
    sl[tid] = accL;
    sw[tid] = accW;
    __syncthreads();
    for (int st = 128; st >= 1; st >>= 1) {
        if (tid < st) { sl[tid] += sl[tid + st]; sw[tid] += sw[tid + st]; }
        __syncthreads();
    }
    if (tid == 0) out[0] = sl[0] / fmaxf(sw[0], 1.0f);
}

// ============================================================================
extern "C" void kernel_launch(void* const* d_in, const int* in_sizes, int n_in,
                              void* d_out, int out_size)
{
    const float* X   = (const float*)d_in[0];
    const float* W   = (const float*)d_in[1];
    const float* msk = (const float*)d_in[2];
    const float* rwd = (const float*)d_in[3];
    const float* bs  = (const float*)d_in[4];
    const float* rX  = (const float*)d_in[5];
    const float* rW  = (const float*)d_in[6];
    const float* rbs = (const float*)d_in[7];
    float* out = (float*)d_out;

    static uint8_t *pWq = nullptr, *prWq, *pXq, *prXq;
    if (!pWq) {
        cudaGetSymbolAddress((void**)&pWq,  g_Wq);
        cudaGetSymbolAddress((void**)&prWq, g_rWq);
        cudaGetSymbolAddress((void**)&pXq,  g_Xq);
        cudaGetSymbolAddress((void**)&prXq, g_rXq);
        cudaFuncSetAttribute(gemm_fp8<true>,  cudaFuncAttributeMaxDynamicSharedMemorySize, SMEM_BYTES);
        cudaFuncSetAttribute(gemm_fp8<false>, cudaFuncAttributeMaxDynamicSharedMemorySize, SMEM_BYTES);
    }

    reset_kernel<<<1, 1>>>();

    const int w4 = V_DIM * H_DIM / 4, x4 = N_TOK * H_DIM / 4;
    split_fp8<<<2048, 256>>>((const float4*)W,  (uint32_t*)pWq,  w4);
    split_fp8<<<2048, 256>>>((const float4*)rW, (uint32_t*)prWq, w4);
    split_fp8<<<512,  256>>>((const float4*)X,  (uint32_t*)pXq,  x4);
    split_fp8<<<512,  256>>>((const float4*)rX, (uint32_t*)prXq, x4);

    dim3 g1(MTILES, NSPLIT);
    gemm_fp8<true ><<<g1, 256, SMEM_BYTES>>>(pXq,  pWq,  bs);
    gemm_fp8<false><<<g1, 256, SMEM_BYTES>>>(prXq, prWq, rbs);

    combine_kernel<<<N_TOK / 8, 256>>>();
    fixup_kernel<<<1024, 128>>>(X, W, bs);
    ref_token_kernel<<<N_TOK, 128>>>(rX, rW, rbs);
    finalize_kernel<<<1, 256>>>(msk, rwd, out);
}

// round 8
// speedup vs baseline: 2.6953x; 1.0816x over previous
#include <cuda_runtime.h>
#include <cuda_fp16.h>
#include <math.h>
#include <stdint.h>

// ---------------- problem constants ----------------
#define N_TOK 2048
#define T_DIM 512
#define H_DIM 2048
#define V_DIM 32000
#define BETAC 0.1f
#define DELTA 0.008f              // argmax window (empirically ~0-1 flips, all benign)
#define FP8_SCALE 64.0f
#define INV_SCALE (1.0f / 4096.0f)   // 1/(64*64)

// ---------------- GEMM tiling ----------------
#define BM 128
#define BN 128
#define BK 64                     // k per stage (fp8 elems, 64B rows)
#define KTILES (H_DIM / BK)       // 32
#define NSPLIT (V_DIM / BN)       // 250
#define NGRP   (V_DIM / 16)       // 2000
#define MTILES (N_TOK / BM)       // 16
#define NSTAGE 4

#define P_A 0
#define P_B 8192
#define STAGE_BYTES 16384
#define SMEM_BYTES (NSTAGE * STAGE_BYTES)   // 64KB/CTA, 2 CTA/SM

#define CAND_CAP (1 << 20)

// ---------------- device scratch ----------------
__device__ uint8_t g_Wq[V_DIM * H_DIM];
__device__ uint8_t g_rWq[V_DIM * H_DIM];
__device__ uint8_t g_Xq[N_TOK * H_DIM];
__device__ uint8_t g_rXq[N_TOK * H_DIM];

__device__ float g_pmax[N_TOK * NGRP];       // [n][group] approx 16-col maxes
__device__ float g_psum[N_TOK * 256];        // [n][split] policy exp-sums
__device__ float g_rsum[N_TOK * 256];        // [n][split] ref exp-sums
__device__ float g_lse[N_TOK];
__device__ unsigned long long g_best[N_TOK]; // packed (orderable fp32 | ~col)
__device__ float g_kl[N_TOK];
__device__ int   g_ccount;
__device__ uint32_t g_cand[CAND_CAP];        // packed n<<11 | group

// ---------------- helpers ----------------
__device__ __forceinline__ uint32_t smem_u32(const void* p) {
    return (uint32_t)__cvta_generic_to_shared(p);
}
// 4 fp32 -> 4 packed e4m3 (x0 in lowest byte)
__device__ __forceinline__ uint32_t cvt4fp8(float x0, float x1, float x2, float x3) {
    uint16_t a, b;
    asm("cvt.rn.satfinite.e4m3x2.f32 %0, %1, %2;" : "=h"(a) : "f"(x1), "f"(x0));
    asm("cvt.rn.satfinite.e4m3x2.f32 %0, %1, %2;" : "=h"(b) : "f"(x3), "f"(x2));
    return (uint32_t)a | ((uint32_t)b << 16);
}
__device__ __forceinline__ void ldsm4(uint32_t* r, uint32_t addr) {
    asm volatile("ldmatrix.sync.aligned.m8n8.x4.shared.b16 {%0,%1,%2,%3}, [%4];"
                 : "=r"(r[0]), "=r"(r[1]), "=r"(r[2]), "=r"(r[3]) : "r"(addr));
}
// fp8 MMA with f16 accumulators
__device__ __forceinline__ void qmma_f16(uint32_t* c, const uint32_t* a,
                                         const uint32_t* b) {
    asm volatile(
        "mma.sync.aligned.m16n8k32.row.col.f16.e4m3.e4m3.f16 "
        "{%0,%1}, {%2,%3,%4,%5}, {%6,%7}, {%0,%1};"
        : "+r"(c[0]), "+r"(c[1])
        : "r"(a[0]), "r"(a[1]), "r"(a[2]), "r"(a[3]), "r"(b[0]), "r"(b[1]));
}
#define CP16(dst, src)                                                       \
    asm volatile("cp.async.cg.shared.global [%0], [%1], 16;" ::              \
                 "r"(dst), "l"(src) : "memory")
#define CP_COMMIT() asm volatile("cp.async.commit_group;" ::: "memory")
#define CP_WAIT()   asm volatile("cp.async.wait_group %0;" :: "n"(NSTAGE - 1) : "memory")

// swizzled byte offset: 64B rows, 16B segs XOR'd -> conflict-free ldmatrix
__device__ __forceinline__ int sw_off(int row, int seg) {
    return row * 64 + ((seg ^ ((row >> 1) & 3)) << 4);
}
__device__ __forceinline__ uint32_t fkey(float f) {   // orderable float bits
    uint32_t u = __float_as_uint(f);
    return (u & 0x80000000u) ? ~u : (u | 0x80000000u);
}

// ============================================================================
__global__ void reset_kernel() { g_ccount = 0; }

// fp32 -> e4m3 (scaled): 1 thread = 4 float4 loads -> 1 uint4 store.
// Exact grid, full occupancy; MLP-4 across many warps -> DRAM-rate bound.
__global__ void split_fp8(const float4* __restrict__ src,
                          uint4* __restrict__ dst, int n16)
{
    const int i = blockIdx.x * blockDim.x + threadIdx.x;
    if (i >= n16) return;
    const float4 a = src[4 * i];
    const float4 b = src[4 * i + 1];
    const float4 c = src[4 * i + 2];
    const float4 d = src[4 * i + 3];
    uint4 o;
    o.x = cvt4fp8(a.x * FP8_SCALE, a.y * FP8_SCALE, a.z * FP8_SCALE, a.w * FP8_SCALE);
    o.y = cvt4fp8(b.x * FP8_SCALE, b.y * FP8_SCALE, b.z * FP8_SCALE, b.w * FP8_SCALE);
    o.z = cvt4fp8(c.x * FP8_SCALE, c.y * FP8_SCALE, c.z * FP8_SCALE, c.w * FP8_SCALE);
    o.w = cvt4fp8(d.x * FP8_SCALE, d.y * FP8_SCALE, d.z * FP8_SCALE, d.w * FP8_SCALE);
    dst[i] = o;
}

// ============================================================================
// e4m3 QMMA GEMM with f16 accumulators (128x128 per CTA, full K),
// cp.async 4-stage pipeline. Epilogue: exp-sum per split; if ARG, group maxes.
// ============================================================================
template <bool ARG>
__global__ void __launch_bounds__(256, 2)
gemm_fp8(const uint8_t* __restrict__ Aq, const uint8_t* __restrict__ Bq,
         const float* __restrict__ bias)
{
    extern __shared__ __align__(1024) char smem[];
    const int tid  = threadIdx.x;
    const int lane = tid & 31;
    const int w    = tid >> 5;
    const int wm   = w & 1;          // M half (64 rows)
    const int wn   = w >> 1;         // N quarter (32 cols)
    const int m0 = blockIdx.x * BM;
    const int v0 = blockIdx.y * BN;
    const uint32_t sb = smem_u32(smem);

    // cp.async loader: 512 segs/plane (128 rows x 4x16B), 2 per thread per plane
    const int s0   = tid << 1;
    const int row0 = s0 >> 2, seg0 = s0 & 3;
    const int row1 = (s0 + 1) >> 2, seg1 = (s0 + 1) & 3;
    const size_t ga0 = (size_t)(m0 + row0) * H_DIM + (seg0 << 4);
    const size_t ga1 = (size_t)(m0 + row1) * H_DIM + (seg1 << 4);
    const size_t gb0 = (size_t)(v0 + row0) * H_DIM + (seg0 << 4);
    const size_t gb1 = (size_t)(v0 + row1) * H_DIM + (seg1 << 4);
    const int so0 = sw_off(row0, seg0);
    const int so1 = sw_off(row1, seg1);

    // ldmatrix base offsets (kk=0; kk=1 is XOR 32)
    const int r_in = lane & 7;
    int offA[4], offB[2];
    {
        const int hm = (lane >> 3) & 1, hk = lane >> 4;
#pragma unroll
        for (int mi = 0; mi < 4; mi++)
            offA[mi] = P_A + sw_off(wm * 64 + mi * 16 + hm * 8 + r_in, hk);
    }
    {
        const int hkb = (lane >> 3) & 1, hn = lane >> 4;
#pragma unroll
        for (int bi = 0; bi < 2; bi++)
            offB[bi] = P_B + sw_off(wn * 32 + bi * 16 + hn * 8 + r_in, hkb);
    }

    uint32_t c[4][4][2];            // f16x2 accumulators
#pragma unroll
    for (int i = 0; i < 4; i++)
#pragma unroll
        for (int j = 0; j < 4; j++) { c[i][j][0] = 0u; c[i][j][1] = 0u; }

    // prologue: fill NSTAGE stages
#pragma unroll
    for (int st = 0; st < NSTAGE; st++) {
        const uint32_t d = sb + st * STAGE_BYTES;
        const int k0 = st * BK;
        CP16(d + P_A + so0, Aq + ga0 + k0);
        CP16(d + P_A + so1, Aq + ga1 + k0);
        CP16(d + P_B + so0, Bq + gb0 + k0);
        CP16(d + P_B + so1, Bq + gb1 + k0);
        CP_COMMIT();
    }

#pragma unroll 1
    for (int kt = 0; kt < KTILES; kt++) {
        const uint32_t stOff = (kt & (NSTAGE - 1)) * STAGE_BYTES;
        CP_WAIT();
        __syncthreads();

#pragma unroll
        for (int kk = 0; kk < 2; kk++) {        // each kk covers k32 (32B)
            const int kx = kk << 5;
            uint32_t Bh[2][4];
#pragma unroll
            for (int bi = 0; bi < 2; bi++)
                ldsm4(Bh[bi], sb + ((offB[bi] + stOff) ^ kx));
#pragma unroll
            for (int mi = 0; mi < 4; mi++) {
                uint32_t Ah[4];
                ldsm4(Ah, sb + ((offA[mi] + stOff) ^ kx));
#pragma unroll
                for (int nf = 0; nf < 4; nf++)
                    qmma_f16(c[mi][nf], Ah, &Bh[nf >> 1][(nf & 1) * 2]);
            }
        }
        __syncthreads();

        if (kt + NSTAGE < KTILES) {
            const uint32_t d = sb + stOff;
            const int k0 = (kt + NSTAGE) * BK;
            CP16(d + P_A + so0, Aq + ga0 + k0);
            CP16(d + P_A + so1, Aq + ga1 + k0);
            CP16(d + P_B + so0, Bq + gb0 + k0);
            CP16(d + P_B + so1, Bq + gb1 + k0);
        }
        CP_COMMIT();
    }

    // ---- epilogue ----
    const int g = lane >> 2, t = lane & 3;
    float sm8[8], mx16[8][2];
#pragma unroll
    for (int i = 0; i < 8; i++) {
        sm8[i] = 0.f;
        mx16[i][0] = -INFINITY;
        mx16[i][1] = -INFINITY;
    }

#pragma unroll
    for (int mi = 0; mi < 4; mi++) {
#pragma unroll
        for (int nf = 0; nf < 4; nf++) {
            const int col0 = wn * 32 + nf * 8 + 2 * t;
            const float b0v = bias[v0 + col0];
            const float b1v = bias[v0 + col0 + 1];
            const float2 lo = __half22float2(*(const __half2*)&c[mi][nf][0]);
            const float2 hi = __half22float2(*(const __half2*)&c[mi][nf][1]);
            const float x00 = lo.x * INV_SCALE + b0v;
            const float x01 = lo.y * INV_SCALE + b1v;
            const float x10 = hi.x * INV_SCALE + b0v;
            const float x11 = hi.y * INV_SCALE + b1v;
            const int sa = mi * 2, sbI = sa + 1;
            sm8[sa]  += __expf(x00) + __expf(x01);
            sm8[sbI] += __expf(x10) + __expf(x11);
            if (ARG) {
                const int h = nf >> 1;
                mx16[sa][h]  = fmaxf(mx16[sa][h],  fmaxf(x00, x01));
                mx16[sbI][h] = fmaxf(mx16[sbI][h], fmaxf(x10, x11));
            }
        }
    }

    // quad reduce over t
#pragma unroll
    for (int i = 0; i < 8; i++) {
        float s = sm8[i];
        s += __shfl_xor_sync(0xFFFFFFFFu, s, 1);
        s += __shfl_xor_sync(0xFFFFFFFFu, s, 2);
        sm8[i] = s;
        if (ARG) {
#pragma unroll
            for (int h = 0; h < 2; h++) {
                float m = mx16[i][h];
                m = fmaxf(m, __shfl_xor_sync(0xFFFFFFFFu, m, 1));
                m = fmaxf(m, __shfl_xor_sync(0xFFFFFFFFu, m, 2));
                mx16[i][h] = m;
            }
        }
    }

    if (ARG && t == 0) {
        const int gb = blockIdx.y * 8 + wn * 2;
#pragma unroll
        for (int mi = 0; mi < 4; mi++)
#pragma unroll
            for (int hr = 0; hr < 2; hr++) {
                const int rowc = wm * 64 + mi * 16 + hr * 8 + g;
                const int i = mi * 2 + hr;
                g_pmax[(size_t)(m0 + rowc) * NGRP + gb]     = mx16[i][0];
                g_pmax[(size_t)(m0 + rowc) * NGRP + gb + 1] = mx16[i][1];
            }
    }

    // sums: cross-warp combine over 4 quarters via smem
    float* rS = (float*)(smem);           // [3][128]
    __syncthreads();
    if (t == 0 && wn != 0) {
#pragma unroll
        for (int mi = 0; mi < 4; mi++)
#pragma unroll
            for (int hr = 0; hr < 2; hr++) {
                const int rowc = wm * 64 + mi * 16 + hr * 8 + g;
                rS[(wn - 1) * 128 + rowc] = sm8[mi * 2 + hr];
            }
    }
    __syncthreads();
    if (t == 0 && wn == 0) {
#pragma unroll
        for (int mi = 0; mi < 4; mi++)
#pragma unroll
            for (int hr = 0; hr < 2; hr++) {
                const int rowc = wm * 64 + mi * 16 + hr * 8 + g;
                float s = sm8[mi * 2 + hr];
#pragma unroll
                for (int q = 0; q < 3; q++) s += rS[q * 128 + rowc];
                if (ARG) g_psum[(size_t)(m0 + rowc) * 256 + blockIdx.y] = s;
                else     g_rsum[(size_t)(m0 + rowc) * 256 + blockIdx.y] = s;
            }
    }
}

// ============================================================================
// Per token (one warp): approx max, lse, init best, emit candidate groups
// ============================================================================
__global__ void combine_kernel() {
    const int lane = threadIdx.x & 31;
    const int n = blockIdx.x * 8 + (threadIdx.x >> 5);

    float m = -INFINITY;
    for (int g = lane; g < NGRP; g += 32)
        m = fmaxf(m, g_pmax[(size_t)n * NGRP + g]);
#pragma unroll
    for (int off = 16; off >= 1; off >>= 1)
        m = fmaxf(m, __shfl_xor_sync(0xFFFFFFFFu, m, off));

    float s = 0.f;
    for (int sp = lane; sp < NSPLIT; sp += 32)
        s += g_psum[(size_t)n * 256 + sp];
#pragma unroll
    for (int off = 16; off >= 1; off >>= 1)
        s += __shfl_xor_sync(0xFFFFFFFFu, s, off);

    if (lane == 0) {
        g_lse[n] = logf(s);
        g_best[n] = 0ULL;
    }

    const float thr = m - DELTA;
    for (int g = lane; g < NGRP; g += 32) {
        const bool c = g_pmax[(size_t)n * NGRP + g] >= thr;
        const unsigned b = __ballot_sync(0xFFFFFFFFu, c);
        if (b == 0) continue;
        int base = 0;
        if (lane == 0) base = atomicAdd(&g_ccount, __popc(b));
        base = __shfl_sync(0xFFFFFFFFu, base, 0);
        if (c) {
            const int idx = base + __popc(b & ((1u << lane) - 1));
            if (idx < CAND_CAP) g_cand[idx] = ((uint32_t)n << 11) | (uint32_t)g;
        }
    }
}

// ============================================================================
// Exact fp32 recompute of candidate 16-col groups; atomicMax packed result
// ============================================================================
__global__ void fixup_kernel(const float* __restrict__ X,
                             const float* __restrict__ W,
                             const float* __restrict__ bias)
{
    int cnt = g_ccount;
    if (cnt > CAND_CAP) cnt = CAND_CAP;
    const int tid = threadIdx.x;
    const int colo = tid >> 3;     // 0..15
    const int sub  = tid & 7;

    for (int i = blockIdx.x; i < cnt; i += gridDim.x) {
        const uint32_t e = g_cand[i];
        const int n = e >> 11;
        const int g = e & 2047;
        const int vcol = g * 16 + colo;
        const float4* xr = (const float4*)(X + (size_t)n * H_DIM);
        const float4* wr = (const float4*)(W + (size_t)vcol * H_DIM);
        float s = 0.f;
#pragma unroll 8
        for (int j = 0; j < 64; j++) {
            const int idx = j * 8 + sub;
            const float4 a = xr[idx], b = wr[idx];
            s += a.x * b.x + a.y * b.y + a.z * b.z + a.w * b.w;
        }
#pragma unroll
        for (int off = 4; off >= 1; off >>= 1)
            s += __shfl_down_sync(0xFFFFFFFFu, s, off, 8);
        if (sub == 0) {
            const float val = s + bias[vcol];
            const unsigned long long pk =
                ((unsigned long long)fkey(val) << 32) |
                (unsigned long long)(0xFFFFFFFFu - (uint32_t)vcol);
            atomicMax(&g_best[n], pk);
        }
    }
}

// ============================================================================
// Per token: decode best, exact ref dot at chosen, ref lse, KL
// ============================================================================
__global__ void ref_token_kernel(const float* __restrict__ refX,
                                 const float* __restrict__ refW,
                                 const float* __restrict__ refBias)
{
    __shared__ float red[128];
    __shared__ float red2[128];
    const int n = blockIdx.x;
    const int tid = threadIdx.x;

    const unsigned long long p = g_best[n];
    const uint32_t key = (uint32_t)(p >> 32);
    const uint32_t ub = (key & 0x80000000u) ? (key & 0x7FFFFFFFu) : ~key;
    const float best_val = __uint_as_float(ub);
    const int chosen = (int)(0xFFFFFFFFu - (uint32_t)(p & 0xFFFFFFFFu));

    const float4* xa = (const float4*)(refX + (size_t)n * H_DIM);
    const float4* wa = (const float4*)(refW + (size_t)chosen * H_DIM);
    float s = 0.f;
#pragma unroll
    for (int i = tid; i < H_DIM / 4; i += 128) {
        const float4 a = xa[i], w = wa[i];
        s += a.x * w.x + a.y * w.y + a.z * w.z + a.w * w.w;
    }
    red[tid] = s;
    float rs = 0.f;
    rs += (tid < NSPLIT) ? g_rsum[(size_t)n * 256 + tid] : 0.f;
    rs += (tid + 128 < NSPLIT) ? g_rsum[(size_t)n * 256 + tid + 128] : 0.f;
    red2[tid] = rs;
    __syncthreads();
    for (int st = 64; st >= 1; st >>= 1) {
        if (tid < st) { red[tid] += red[tid + st]; red2[tid] += red2[tid + st]; }
        __syncthreads();
    }
    if (tid == 0) {
        const float ref_logit = red[0] + refBias[chosen];
        const float tok_lp = best_val - g_lse[n];
        const float d = (ref_logit - logf(red2[0])) - tok_lp;
        g_kl[n] = expm1f(d) - d;
    }
}

// ============================================================================
__global__ void finalize_kernel(const float* __restrict__ mask,
                                const float* __restrict__ rewards,
                                float* __restrict__ out)
{
    __shared__ float sl[256];
    __shared__ float sw[256];
    const int tid = threadIdx.x;
    const double r0 = rewards[0], r1 = rewards[1], r2 = rewards[2], r3 = rewards[3];
    const double mean = (r0 + r1 + r2 + r3) * 0.25;
    const double d0 = r0 - mean, d1 = r1 - mean, d2 = r2 - mean, d3 = r3 - mean;
    const double sd = sqrt((d0 * d0 + d1 * d1 + d2 * d2 + d3 * d3) / 3.0) + 1e-4;
    const float adv[4] = {(float)(d0 / sd), (float)(d1 / sd),
                          (float)(d2 / sd), (float)(d3 / sd)};
    float accL = 0.f, accW = 0.f;
    for (int n = tid; n < N_TOK; n += 256) {
        const float mk = mask[n];
        const int b = n / T_DIM;
        accL += (BETAC * g_kl[n] - adv[b]) * mk;
        accW += mk;
    }
    sl[tid] = accL;
    sw[tid] = accW;
    __syncthreads();
    for (int st = 128; st >= 1; st >>= 1) {
        if (tid < st) { sl[tid] += sl[tid + st]; sw[tid] += sw[tid + st]; }
        __syncthreads();
    }
    if (tid == 0) out[0] = sl[0] / fmaxf(sw[0], 1.0f);
}

// ============================================================================
extern "C" void kernel_launch(void* const* d_in, const int* in_sizes, int n_in,
                              void* d_out, int out_size)
{
    const float* X   = (const float*)d_in[0];
    const float* W   = (const float*)d_in[1];
    const float* msk = (const float*)d_in[2];
    const float* rwd = (const float*)d_in[3];
    const float* bs  = (const float*)d_in[4];
    const float* rX  = (const float*)d_in[5];
    const float* rW  = (const float*)d_in[6];
    const float* rbs = (const float*)d_in[7];
    float* out = (float*)d_out;

    static uint8_t *pWq = nullptr, *prWq, *pXq, *prXq;
    static cudaStream_t s1 = nullptr;
    static cudaEvent_t evF = nullptr, evJ = nullptr;
    if (!pWq) {
        cudaGetSymbolAddress((void**)&pWq,  g_Wq);
        cudaGetSymbolAddress((void**)&prWq, g_rWq);
        cudaGetSymbolAddress((void**)&pXq,  g_Xq);
        cudaGetSymbolAddress((void**)&prXq, g_rXq);
        cudaFuncSetAttribute(gemm_fp8<true>,  cudaFuncAttributeMaxDynamicSharedMemorySize, SMEM_BYTES);
        cudaFuncSetAttribute(gemm_fp8<false>, cudaFuncAttributeMaxDynamicSharedMemorySize, SMEM_BYTES);
        cudaStreamCreateWithFlags(&s1, cudaStreamNonBlocking);
        cudaEventCreateWithFlags(&evF, cudaEventDisableTiming);
        cudaEventCreateWithFlags(&evJ, cudaEventDisableTiming);
    }

    const int w16 = V_DIM * H_DIM / 16;   // 4,096,000 threads -> 16000 blocks
    const int x16 = N_TOK * H_DIM / 16;   // 262,144 threads  -> 1024 blocks
    dim3 g1(MTILES, NSPLIT);

    // ---- fork: ref pipeline on s1 (split rW/rX -> gemm_ref) ----
    cudaEventRecord(evF, 0);
    cudaStreamWaitEvent(s1, evF, 0);
    split_fp8<<<w16 / 256, 256, 0, s1>>>((const float4*)rW, (uint4*)prWq, w16);
    split_fp8<<<x16 / 256, 256, 0, s1>>>((const float4*)rX, (uint4*)prXq, x16);
    gemm_fp8<false><<<g1, 256, SMEM_BYTES, s1>>>(prXq, prWq, rbs);
    cudaEventRecord(evJ, s1);

    // ---- policy pipeline on default stream ----
    reset_kernel<<<1, 1>>>();
    split_fp8<<<w16 / 256, 256>>>((const float4*)W, (uint4*)pWq, w16);
    split_fp8<<<x16 / 256, 256>>>((const float4*)X, (uint4*)pXq, x16);
    gemm_fp8<true><<<g1, 256, SMEM_BYTES>>>(pXq, pWq, bs);
    combine_kernel<<<N_TOK / 8, 256>>>();
    fixup_kernel<<<1024, 128>>>(X, W, bs);

    // ---- join: tail needs both pipelines ----
    cudaStreamWaitEvent(0, evJ, 0);
    ref_token_kernel<<<N_TOK, 128>>>(rX, rW, rbs);
    finalize_kernel<<<1, 256>>>(msk, rwd, out);
}

// round 9
// speedup vs baseline: 2.7394x; 1.0164x over previous
#include <cuda_runtime.h>
#include <cuda_fp16.h>
#include <math.h>
#include <stdint.h>

// ---------------- problem constants ----------------
#define N_TOK 2048
#define T_DIM 512
#define H_DIM 2048
#define V_DIM 32000
#define BETAC 0.1f
#define DELTA 0.008f
#define FP8_SCALE 64.0f
#define INV_SCALE (1.0f / 4096.0f)   // 1/(64*64)

// ---------------- GEMM tiling ----------------
#define BM 128
#define BN 128
#define BK 64                     // k per stage (fp8 elems, 64B rows)
#define KTILES (H_DIM / BK)       // 32
#define NSPLIT (V_DIM / BN)       // 250
#define NGRP   (V_DIM / 16)       // 2000
#define MTILES (N_TOK / BM)       // 16
#define NSTAGE 4

#define P_A 0
#define P_B 8192
#define STAGE_BYTES 16384
#define SMEM_BYTES (NSTAGE * STAGE_BYTES)   // 64KB/CTA, 2 CTA/SM

#define CAND_CAP (1 << 20)

// ---------------- device scratch ----------------
__device__ uint8_t g_Wq[V_DIM * H_DIM];
__device__ uint8_t g_rWq[V_DIM * H_DIM];
__device__ uint8_t g_Xq[N_TOK * H_DIM];
__device__ uint8_t g_rXq[N_TOK * H_DIM];

__device__ float g_pmax[N_TOK * NGRP];       // [n][group] approx 16-col maxes
__device__ float g_psum[N_TOK * 256];        // [n][split] policy exp-sums
__device__ float g_rsum[N_TOK * 256];        // [n][split] ref exp-sums
__device__ float g_lse[N_TOK];
__device__ unsigned long long g_best[N_TOK]; // packed (orderable fp32 | ~col)
__device__ float g_kl[N_TOK];
__device__ int   g_ccount;
__device__ uint32_t g_cand[CAND_CAP];        // packed n<<11 | group

// ---------------- helpers ----------------
__device__ __forceinline__ uint32_t smem_u32(const void* p) {
    return (uint32_t)__cvta_generic_to_shared(p);
}
// 4 fp32 -> 4 packed e4m3 (x0 in lowest byte)
__device__ __forceinline__ uint32_t cvt4fp8(float x0, float x1, float x2, float x3) {
    uint16_t a, b;
    asm("cvt.rn.satfinite.e4m3x2.f32 %0, %1, %2;" : "=h"(a) : "f"(x1), "f"(x0));
    asm("cvt.rn.satfinite.e4m3x2.f32 %0, %1, %2;" : "=h"(b) : "f"(x3), "f"(x2));
    return (uint32_t)a | ((uint32_t)b << 16);
}
__device__ __forceinline__ void ldsm4(uint32_t* r, uint32_t addr) {
    asm volatile("ldmatrix.sync.aligned.m8n8.x4.shared.b16 {%0,%1,%2,%3}, [%4];"
                 : "=r"(r[0]), "=r"(r[1]), "=r"(r[2]), "=r"(r[3]) : "r"(addr));
}
// fp8 MMA with f16 accumulators
__device__ __forceinline__ void qmma_f16(uint32_t* c, const uint32_t* a,
                                         const uint32_t* b) {
    asm volatile(
        "mma.sync.aligned.m16n8k32.row.col.f16.e4m3.e4m3.f16 "
        "{%0,%1}, {%2,%3,%4,%5}, {%6,%7}, {%0,%1};"
        : "+r"(c[0]), "+r"(c[1])
        : "r"(a[0]), "r"(a[1]), "r"(a[2]), "r"(a[3]), "r"(b[0]), "r"(b[1]));
}
#define CP16(dst, src)                                                       \
    asm volatile("cp.async.cg.shared.global [%0], [%1], 16;" ::              \
                 "r"(dst), "l"(src) : "memory")
#define CP_COMMIT() asm volatile("cp.async.commit_group;" ::: "memory")
#define CP_WAIT()   asm volatile("cp.async.wait_group %0;" :: "n"(NSTAGE - 1) : "memory")

// swizzled byte offset: 64B rows, 16B segs XOR'd -> conflict-free ldmatrix
__device__ __forceinline__ int sw_off(int row, int seg) {
    return row * 64 + ((seg ^ ((row >> 1) & 3)) << 4);
}
__device__ __forceinline__ uint32_t fkey(float f) {   // orderable float bits
    uint32_t u = __float_as_uint(f);
    return (u & 0x80000000u) ? ~u : (u | 0x80000000u);
}

// ============================================================================
__global__ void reset_kernel() { g_ccount = 0; }

// fp32 -> e4m3 (scaled): 1 thread = 4 float4 loads -> 1 uint4 store.
__global__ void split_fp8(const float4* __restrict__ src,
                          uint4* __restrict__ dst, int n16)
{
    const int i = blockIdx.x * blockDim.x + threadIdx.x;
    if (i >= n16) return;
    const float4 a = src[4 * i];
    const float4 b = src[4 * i + 1];
    const float4 c = src[4 * i + 2];
    const float4 d = src[4 * i + 3];
    uint4 o;
    o.x = cvt4fp8(a.x * FP8_SCALE, a.y * FP8_SCALE, a.z * FP8_SCALE, a.w * FP8_SCALE);
    o.y = cvt4fp8(b.x * FP8_SCALE, b.y * FP8_SCALE, b.z * FP8_SCALE, b.w * FP8_SCALE);
    o.z = cvt4fp8(c.x * FP8_SCALE, c.y * FP8_SCALE, c.z * FP8_SCALE, c.w * FP8_SCALE);
    o.w = cvt4fp8(d.x * FP8_SCALE, d.y * FP8_SCALE, d.z * FP8_SCALE, d.w * FP8_SCALE);
    dst[i] = o;
}

// ============================================================================
// e4m3 QMMA GEMM with f16 accumulators (128x128 per CTA, full K),
// cp.async 4-stage pipeline. Epilogue: exp-sum per split; if ARG, group maxes.
// ============================================================================
template <bool ARG>
__global__ void __launch_bounds__(256, 2)
gemm_fp8(const uint8_t* __restrict__ Aq, const uint8_t* __restrict__ Bq,
         const float* __restrict__ bias)
{
    extern __shared__ __align__(1024) char smem[];
    const int tid  = threadIdx.x;
    const int lane = tid & 31;
    const int w    = tid >> 5;
    const int wm   = w & 1;          // M half (64 rows)
    const int wn   = w >> 1;         // N quarter (32 cols)
    const int m0 = blockIdx.x * BM;
    const int v0 = blockIdx.y * BN;
    const uint32_t sb = smem_u32(smem);

    // cp.async loader: 512 segs/plane (128 rows x 4x16B), 2 per thread per plane
    const int s0   = tid << 1;
    const int row0 = s0 >> 2, seg0 = s0 & 3;
    const int row1 = (s0 + 1) >> 2, seg1 = (s0 + 1) & 3;
    const size_t ga0 = (size_t)(m0 + row0) * H_DIM + (seg0 << 4);
    const size_t ga1 = (size_t)(m0 + row1) * H_DIM + (seg1 << 4);
    const size_t gb0 = (size_t)(v0 + row0) * H_DIM + (seg0 << 4);
    const size_t gb1 = (size_t)(v0 + row1) * H_DIM + (seg1 << 4);
    const int so0 = sw_off(row0, seg0);
    const int so1 = sw_off(row1, seg1);

    // ldmatrix base offsets (kk=0; kk=1 is XOR 32)
    const int r_in = lane & 7;
    int offA[4], offB[2];
    {
        const int hm = (lane >> 3) & 1, hk = lane >> 4;
#pragma unroll
        for (int mi = 0; mi < 4; mi++)
            offA[mi] = P_A + sw_off(wm * 64 + mi * 16 + hm * 8 + r_in, hk);
    }
    {
        const int hkb = (lane >> 3) & 1, hn = lane >> 4;
#pragma unroll
        for (int bi = 0; bi < 2; bi++)
            offB[bi] = P_B + sw_off(wn * 32 + bi * 16 + hn * 8 + r_in, hkb);
    }

    uint32_t c[4][4][2];            // f16x2 accumulators
#pragma unroll
    for (int i = 0; i < 4; i++)
#pragma unroll
        for (int j = 0; j < 4; j++) { c[i][j][0] = 0u; c[i][j][1] = 0u; }

    // prologue: fill NSTAGE stages
#pragma unroll
    for (int st = 0; st < NSTAGE; st++) {
        const uint32_t d = sb + st * STAGE_BYTES;
        const int k0 = st * BK;
        CP16(d + P_A + so0, Aq + ga0 + k0);
        CP16(d + P_A + so1, Aq + ga1 + k0);
        CP16(d + P_B + so0, Bq + gb0 + k0);
        CP16(d + P_B + so1, Bq + gb1 + k0);
        CP_COMMIT();
    }

#pragma unroll 1
    for (int kt = 0; kt < KTILES; kt++) {
        const uint32_t stOff = (kt & (NSTAGE - 1)) * STAGE_BYTES;
        CP_WAIT();
        __syncthreads();

#pragma unroll
        for (int kk = 0; kk < 2; kk++) {        // each kk covers k32 (32B)
            const int kx = kk << 5;
            uint32_t Bh[2][4];
#pragma unroll
            for (int bi = 0; bi < 2; bi++)
                ldsm4(Bh[bi], sb + ((offB[bi] + stOff) ^ kx));
#pragma unroll
            for (int mi = 0; mi < 4; mi++) {
                uint32_t Ah[4];
                ldsm4(Ah, sb + ((offA[mi] + stOff) ^ kx));
#pragma unroll
                for (int nf = 0; nf < 4; nf++)
                    qmma_f16(c[mi][nf], Ah, &Bh[nf >> 1][(nf & 1) * 2]);
            }
        }
        __syncthreads();

        if (kt + NSTAGE < KTILES) {
            const uint32_t d = sb + stOff;
            const int k0 = (kt + NSTAGE) * BK;
            CP16(d + P_A + so0, Aq + ga0 + k0);
            CP16(d + P_A + so1, Aq + ga1 + k0);
            CP16(d + P_B + so0, Bq + gb0 + k0);
            CP16(d + P_B + so1, Bq + gb1 + k0);
        }
        CP_COMMIT();
    }

    // ---- epilogue ----
    const int g = lane >> 2, t = lane & 3;
    float sm8[8], mx16[8][2];
#pragma unroll
    for (int i = 0; i < 8; i++) {
        sm8[i] = 0.f;
        mx16[i][0] = -INFINITY;
        mx16[i][1] = -INFINITY;
    }

#pragma unroll
    for (int mi = 0; mi < 4; mi++) {
#pragma unroll
        for (int nf = 0; nf < 4; nf++) {
            const int col0 = wn * 32 + nf * 8 + 2 * t;
            const float b0v = bias[v0 + col0];
            const float b1v = bias[v0 + col0 + 1];
            const float2 lo = __half22float2(*(const __half2*)&c[mi][nf][0]);
            const float2 hi = __half22float2(*(const __half2*)&c[mi][nf][1]);
            const float x00 = lo.x * INV_SCALE + b0v;
            const float x01 = lo.y * INV_SCALE + b1v;
            const float x10 = hi.x * INV_SCALE + b0v;
            const float x11 = hi.y * INV_SCALE + b1v;
            const int sa = mi * 2, sbI = sa + 1;
            sm8[sa]  += __expf(x00) + __expf(x01);
            sm8[sbI] += __expf(x10) + __expf(x11);
            if (ARG) {
                const int h = nf >> 1;
                mx16[sa][h]  = fmaxf(mx16[sa][h],  fmaxf(x00, x01));
                mx16[sbI][h] = fmaxf(mx16[sbI][h], fmaxf(x10, x11));
            }
        }
    }

    // quad reduce over t
#pragma unroll
    for (int i = 0; i < 8; i++) {
        float s = sm8[i];
        s += __shfl_xor_sync(0xFFFFFFFFu, s, 1);
        s += __shfl_xor_sync(0xFFFFFFFFu, s, 2);
        sm8[i] = s;
        if (ARG) {
#pragma unroll
            for (int h = 0; h < 2; h++) {
                float m = mx16[i][h];
                m = fmaxf(m, __shfl_xor_sync(0xFFFFFFFFu, m, 1));
                m = fmaxf(m, __shfl_xor_sync(0xFFFFFFFFu, m, 2));
                mx16[i][h] = m;
            }
        }
    }

    if (ARG && t == 0) {
        const int gb = blockIdx.y * 8 + wn * 2;
#pragma unroll
        for (int mi = 0; mi < 4; mi++)
#pragma unroll
            for (int hr = 0; hr < 2; hr++) {
                const int rowc = wm * 64 + mi * 16 + hr * 8 + g;
                const int i = mi * 2 + hr;
                g_pmax[(size_t)(m0 + rowc) * NGRP + gb]     = mx16[i][0];
                g_pmax[(size_t)(m0 + rowc) * NGRP + gb + 1] = mx16[i][1];
            }
    }

    // sums: cross-warp combine over 4 quarters via smem
    float* rS = (float*)(smem);           // [3][128]
    __syncthreads();
    if (t == 0 && wn != 0) {
#pragma unroll
        for (int mi = 0; mi < 4; mi++)
#pragma unroll
            for (int hr = 0; hr < 2; hr++) {
                const int rowc = wm * 64 + mi * 16 + hr * 8 + g;
                rS[(wn - 1) * 128 + rowc] = sm8[mi * 2 + hr];
            }
    }
    __syncthreads();
    if (t == 0 && wn == 0) {
#pragma unroll
        for (int mi = 0; mi < 4; mi++)
#pragma unroll
            for (int hr = 0; hr < 2; hr++) {
                const int rowc = wm * 64 + mi * 16 + hr * 8 + g;
                float s = sm8[mi * 2 + hr];
#pragma unroll
                for (int q = 0; q < 3; q++) s += rS[q * 128 + rowc];
                if (ARG) g_psum[(size_t)(m0 + rowc) * 256 + blockIdx.y] = s;
                else     g_rsum[(size_t)(m0 + rowc) * 256 + blockIdx.y] = s;
            }
    }
}

// ============================================================================
// Per token (one warp): approx max, lse, init best, emit candidate groups
// ============================================================================
__global__ void combine_kernel() {
    const int lane = threadIdx.x & 31;
    const int n = blockIdx.x * 8 + (threadIdx.x >> 5);

    float m = -INFINITY;
    for (int g = lane; g < NGRP; g += 32)
        m = fmaxf(m, g_pmax[(size_t)n * NGRP + g]);
#pragma unroll
    for (int off = 16; off >= 1; off >>= 1)
        m = fmaxf(m, __shfl_xor_sync(0xFFFFFFFFu, m, off));

    float s = 0.f;
    for (int sp = lane; sp < NSPLIT; sp += 32)
        s += g_psum[(size_t)n * 256 + sp];
#pragma unroll
    for (int off = 16; off >= 1; off >>= 1)
        s += __shfl_xor_sync(0xFFFFFFFFu, s, off);

    if (lane == 0) {
        g_lse[n] = logf(s);
        g_best[n] = 0ULL;
    }

    const float thr = m - DELTA;
    for (int g = lane; g < NGRP; g += 32) {
        const bool c = g_pmax[(size_t)n * NGRP + g] >= thr;
        const unsigned b = __ballot_sync(0xFFFFFFFFu, c);
        if (b == 0) continue;
        int base = 0;
        if (lane == 0) base = atomicAdd(&g_ccount, __popc(b));
        base = __shfl_sync(0xFFFFFFFFu, base, 0);
        if (c) {
            const int idx = base + __popc(b & ((1u << lane) - 1));
            if (idx < CAND_CAP) g_cand[idx] = ((uint32_t)n << 11) | (uint32_t)g;
        }
    }
}

// ============================================================================
// Exact fp32 recompute of candidate 16-col groups; atomicMax packed result
// ============================================================================
__global__ void fixup_kernel(const float* __restrict__ X,
                             const float* __restrict__ W,
                             const float* __restrict__ bias)
{
    int cnt = g_ccount;
    if (cnt > CAND_CAP) cnt = CAND_CAP;
    const int tid = threadIdx.x;
    const int colo = tid >> 3;     // 0..15
    const int sub  = tid & 7;

    for (int i = blockIdx.x; i < cnt; i += gridDim.x) {
        const uint32_t e = g_cand[i];
        const int n = e >> 11;
        const int g = e & 2047;
        const int vcol = g * 16 + colo;
        const float4* xr = (const float4*)(X + (size_t)n * H_DIM);
        const float4* wr = (const float4*)(W + (size_t)vcol * H_DIM);
        float s = 0.f;
#pragma unroll 8
        for (int j = 0; j < 64; j++) {
            const int idx = j * 8 + sub;
            const float4 a = xr[idx], b = wr[idx];
            s += a.x * b.x + a.y * b.y + a.z * b.z + a.w * b.w;
        }
#pragma unroll
        for (int off = 4; off >= 1; off >>= 1)
            s += __shfl_down_sync(0xFFFFFFFFu, s, off, 8);
        if (sub == 0) {
            const float val = s + bias[vcol];
            const unsigned long long pk =
                ((unsigned long long)fkey(val) << 32) |
                (unsigned long long)(0xFFFFFFFFu - (uint32_t)vcol);
            atomicMax(&g_best[n], pk);
        }
    }
}

// ============================================================================
// Per token: decode best, exact ref dot at chosen, ref lse, KL
// ============================================================================
__global__ void ref_token_kernel(const float* __restrict__ refX,
                                 const float* __restrict__ refW,
                                 const float* __restrict__ refBias)
{
    __shared__ float red[128];
    __shared__ float red2[128];
    const int n = blockIdx.x;
    const int tid = threadIdx.x;

    const unsigned long long p = g_best[n];
    const uint32_t key = (uint32_t)(p >> 32);
    const uint32_t ub = (key & 0x80000000u) ? (key & 0x7FFFFFFFu) : ~key;
    const float best_val = __uint_as_float(ub);
    const int chosen = (int)(0xFFFFFFFFu - (uint32_t)(p & 0xFFFFFFFFu));

    const float4* xa = (const float4*)(refX + (size_t)n * H_DIM);
    const float4* wa = (const float4*)(refW + (size_t)chosen * H_DIM);
    float s = 0.f;
#pragma unroll
    for (int i = tid; i < H_DIM / 4; i += 128) {
        const float4 a = xa[i], w = wa[i];
        s += a.x * w.x + a.y * w.y + a.z * w.z + a.w * w.w;
    }
    red[tid] = s;
    float rs = 0.f;
    rs += (tid < NSPLIT) ? g_rsum[(size_t)n * 256 + tid] : 0.f;
    rs += (tid + 128 < NSPLIT) ? g_rsum[(size_t)n * 256 + tid + 128] : 0.f;
    red2[tid] = rs;
    __syncthreads();
    for (int st = 64; st >= 1; st >>= 1) {
        if (tid < st) { red[tid] += red[tid + st]; red2[tid] += red2[tid + st]; }
        __syncthreads();
    }
    if (tid == 0) {
        const float ref_logit = red[0] + refBias[chosen];
        const float tok_lp = best_val - g_lse[n];
        const float d = (ref_logit - logf(red2[0])) - tok_lp;
        g_kl[n] = expm1f(d) - d;
    }
}

// ============================================================================
__global__ void finalize_kernel(const float* __restrict__ mask,
                                const float* __restrict__ rewards,
                                float* __restrict__ out)
{
    __shared__ float sl[256];
    __shared__ float sw[256];
    const int tid = threadIdx.x;
    const double r0 = rewards[0], r1 = rewards[1], r2 = rewards[2], r3 = rewards[3];
    const double mean = (r0 + r1 + r2 + r3) * 0.25;
    const double d0 = r0 - mean, d1 = r1 - mean, d2 = r2 - mean, d3 = r3 - mean;
    const double sd = sqrt((d0 * d0 + d1 * d1 + d2 * d2 + d3 * d3) / 3.0) + 1e-4;
    const float adv[4] = {(float)(d0 / sd), (float)(d1 / sd),
                          (float)(d2 / sd), (float)(d3 / sd)};
    float accL = 0.f, accW = 0.f;
    for (int n = tid; n < N_TOK; n += 256) {
        const float mk = mask[n];
        const int b = n / T_DIM;
        accL += (BETAC * g_kl[n] - adv[b]) * mk;
        accW += mk;
    }
    sl[tid] = accL;
    sw[tid] = accW;
    __syncthreads();
    for (int st = 128; st >= 1; st >>= 1) {
        if (tid < st) { sl[tid] += sl[tid + st]; sw[tid] += sw[tid + st]; }
        __syncthreads();
    }
    if (tid == 0) out[0] = sl[0] / fmaxf(sw[0], 1.0f);
}

// ============================================================================
extern "C" void kernel_launch(void* const* d_in, const int* in_sizes, int n_in,
                              void* d_out, int out_size)
{
    const float* X   = (const float*)d_in[0];
    const float* W   = (const float*)d_in[1];
    const float* msk = (const float*)d_in[2];
    const float* rwd = (const float*)d_in[3];
    const float* bs  = (const float*)d_in[4];
    const float* rX  = (const float*)d_in[5];
    const float* rW  = (const float*)d_in[6];
    const float* rbs = (const float*)d_in[7];
    float* out = (float*)d_out;

    static uint8_t *pWq = nullptr, *prWq, *pXq, *prXq;
    static cudaStream_t s1 = nullptr;
    static cudaEvent_t evF = nullptr, evP = nullptr, evJ = nullptr;
    if (!pWq) {
        cudaGetSymbolAddress((void**)&pWq,  g_Wq);
        cudaGetSymbolAddress((void**)&prWq, g_rWq);
        cudaGetSymbolAddress((void**)&pXq,  g_Xq);
        cudaGetSymbolAddress((void**)&prXq, g_rXq);
        cudaFuncSetAttribute(gemm_fp8<true>,  cudaFuncAttributeMaxDynamicSharedMemorySize, SMEM_BYTES);
        cudaFuncSetAttribute(gemm_fp8<false>, cudaFuncAttributeMaxDynamicSharedMemorySize, SMEM_BYTES);
        cudaStreamCreateWithFlags(&s1, cudaStreamNonBlocking);
        cudaEventCreateWithFlags(&evF, cudaEventDisableTiming);
        cudaEventCreateWithFlags(&evP, cudaEventDisableTiming);
        cudaEventCreateWithFlags(&evJ, cudaEventDisableTiming);
    }

    const int w16 = V_DIM * H_DIM / 16;   // 16000 blocks
    const int x16 = N_TOK * H_DIM / 16;   // 1024 blocks
    dim3 g1(MTILES, NSPLIT);

    // ---- fork: ref splits run concurrently with policy splits ----
    cudaEventRecord(evF, 0);
    cudaStreamWaitEvent(s1, evF, 0);
    split_fp8<<<w16 / 256, 256, 0, s1>>>((const float4*)rW, (uint4*)prWq, w16);
    split_fp8<<<x16 / 256, 256, 0, s1>>>((const float4*)rX, (uint4*)prXq, x16);

    // ---- policy pipeline on default stream ----
    reset_kernel<<<1, 1>>>();
    split_fp8<<<w16 / 256, 256>>>((const float4*)W, (uint4*)pWq, w16);
    split_fp8<<<x16 / 256, 256>>>((const float4*)X, (uint4*)pXq, x16);
    gemm_fp8<true><<<g1, 256, SMEM_BYTES>>>(pXq, pWq, bs);
    cudaEventRecord(evP, 0);   // gemm_p done

    // ---- gemm_r starts only after gemm_p (no tensor-pipe sharing);
    //      combine+fixup then overlap with gemm_r ----
    cudaStreamWaitEvent(s1, evP, 0);
    gemm_fp8<false><<<g1, 256, SMEM_BYTES, s1>>>(prXq, prWq, rbs);
    cudaEventRecord(evJ, s1);

    combine_kernel<<<N_TOK / 8, 256>>>();
    fixup_kernel<<<2048, 128>>>(X, W, bs);

    // ---- join: tail needs both pipelines ----
    cudaStreamWaitEvent(0, evJ, 0);
    ref_token_kernel<<<N_TOK, 128>>>(rX, rW, rbs);
    finalize_kernel<<<1, 256>>>(msk, rwd, out);
}

// round 10
// speedup vs baseline: 2.7741x; 1.0126x over previous
#include <cuda_runtime.h>
#include <cuda_fp16.h>
#include <math.h>
#include <stdint.h>

// ---------------- problem constants ----------------
#define N_TOK 2048
#define T_DIM 512
#define H_DIM 2048
#define V_DIM 32000
#define BETAC 0.1f
#define DELTA 0.008f
#define FP8_SCALE 64.0f
#define INV_SCALE (1.0f / 4096.0f)   // 1/(64*64)

// ---------------- GEMM tiling ----------------
#define BM 128
#define BN 128
#define BK 64                     // k per stage (fp8 elems, 64B rows)
#define KTILES (H_DIM / BK)       // 32
#define NSPLIT (V_DIM / BN)       // 250
#define NGRP   (V_DIM / 16)       // 2000
#define MTILES (N_TOK / BM)       // 16
#define NSTAGE 4

#define P_A 0
#define P_B 8192
#define STAGE_BYTES 16384
#define SMEM_BYTES (NSTAGE * STAGE_BYTES)   // 64KB/CTA, 2 CTA/SM

#define CAND_CAP (1 << 20)

// ---------------- device scratch ----------------
__device__ uint8_t g_Wq[V_DIM * H_DIM];
__device__ uint8_t g_rWq[V_DIM * H_DIM];
__device__ uint8_t g_Xq[N_TOK * H_DIM];
__device__ uint8_t g_rXq[N_TOK * H_DIM];

__device__ float g_pmax[N_TOK * NGRP];       // [n][group] approx 16-col maxes
__device__ float g_psum[N_TOK * 256];        // [n][split] policy exp-sums
__device__ float g_rsum[N_TOK * 256];        // [n][split] ref exp-sums
__device__ float g_lse[N_TOK];
__device__ unsigned long long g_best[N_TOK]; // packed (orderable fp32 | ~col)
__device__ float g_reflogit[N_TOK];
__device__ float g_kl[N_TOK];
__device__ int   g_ccount;
__device__ uint32_t g_cand[CAND_CAP];        // packed n<<11 | group

// ---------------- helpers ----------------
__device__ __forceinline__ uint32_t smem_u32(const void* p) {
    return (uint32_t)__cvta_generic_to_shared(p);
}
// 4 fp32 -> 4 packed e4m3 (x0 in lowest byte)
__device__ __forceinline__ uint32_t cvt4fp8(float x0, float x1, float x2, float x3) {
    uint16_t a, b;
    asm("cvt.rn.satfinite.e4m3x2.f32 %0, %1, %2;" : "=h"(a) : "f"(x1), "f"(x0));
    asm("cvt.rn.satfinite.e4m3x2.f32 %0, %1, %2;" : "=h"(b) : "f"(x3), "f"(x2));
    return (uint32_t)a | ((uint32_t)b << 16);
}
__device__ __forceinline__ void ldsm4(uint32_t* r, uint32_t addr) {
    asm volatile("ldmatrix.sync.aligned.m8n8.x4.shared.b16 {%0,%1,%2,%3}, [%4];"
                 : "=r"(r[0]), "=r"(r[1]), "=r"(r[2]), "=r"(r[3]) : "r"(addr));
}
// fp8 MMA with f16 accumulators
__device__ __forceinline__ void qmma_f16(uint32_t* c, const uint32_t* a,
                                         const uint32_t* b) {
    asm volatile(
        "mma.sync.aligned.m16n8k32.row.col.f16.e4m3.e4m3.f16 "
        "{%0,%1}, {%2,%3,%4,%5}, {%6,%7}, {%0,%1};"
        : "+r"(c[0]), "+r"(c[1])
        : "r"(a[0]), "r"(a[1]), "r"(a[2]), "r"(a[3]), "r"(b[0]), "r"(b[1]));
}
#define CP16(dst, src)                                                       \
    asm volatile("cp.async.cg.shared.global [%0], [%1], 16;" ::              \
                 "r"(dst), "l"(src) : "memory")
#define CP_COMMIT() asm volatile("cp.async.commit_group;" ::: "memory")
#define CP_WAIT()   asm volatile("cp.async.wait_group %0;" :: "n"(NSTAGE - 1) : "memory")

// swizzled byte offset: 64B rows, 16B segs XOR'd -> conflict-free ldmatrix
__device__ __forceinline__ int sw_off(int row, int seg) {
    return row * 64 + ((seg ^ ((row >> 1) & 3)) << 4);
}
__device__ __forceinline__ uint32_t fkey(float f) {   // orderable float bits
    uint32_t u = __float_as_uint(f);
    return (u & 0x80000000u) ? ~u : (u | 0x80000000u);
}

// ============================================================================
__global__ void reset_kernel() { g_ccount = 0; }

// fp32 -> e4m3 (scaled): 1 thread = 4 float4 loads -> 1 uint4 store.
__global__ void split_fp8(const float4* __restrict__ src,
                          uint4* __restrict__ dst, int n16)
{
    const int i = blockIdx.x * blockDim.x + threadIdx.x;
    if (i >= n16) return;
    const float4 a = src[4 * i];
    const float4 b = src[4 * i + 1];
    const float4 c = src[4 * i + 2];
    const float4 d = src[4 * i + 3];
    uint4 o;
    o.x = cvt4fp8(a.x * FP8_SCALE, a.y * FP8_SCALE, a.z * FP8_SCALE, a.w * FP8_SCALE);
    o.y = cvt4fp8(b.x * FP8_SCALE, b.y * FP8_SCALE, b.z * FP8_SCALE, b.w * FP8_SCALE);
    o.z = cvt4fp8(c.x * FP8_SCALE, c.y * FP8_SCALE, c.z * FP8_SCALE, c.w * FP8_SCALE);
    o.w = cvt4fp8(d.x * FP8_SCALE, d.y * FP8_SCALE, d.z * FP8_SCALE, d.w * FP8_SCALE);
    dst[i] = o;
}

// ============================================================================
// e4m3 QMMA GEMM with f16 accumulators (128x128 per CTA, full K),
// cp.async 4-stage pipeline. Epilogue: exp-sum per split; if ARG, group maxes.
// ============================================================================
template <bool ARG>
__global__ void __launch_bounds__(256, 2)
gemm_fp8(const uint8_t* __restrict__ Aq, const uint8_t* __restrict__ Bq,
         const float* __restrict__ bias)
{
    extern __shared__ __align__(1024) char smem[];
    const int tid  = threadIdx.x;
    const int lane = tid & 31;
    const int w    = tid >> 5;
    const int wm   = w & 1;          // M half (64 rows)
    const int wn   = w >> 1;         // N quarter (32 cols)
    const int m0 = blockIdx.x * BM;
    const int v0 = blockIdx.y * BN;
    const uint32_t sb = smem_u32(smem);

    // cp.async loader: 512 segs/plane (128 rows x 4x16B), 2 per thread per plane
    const int s0   = tid << 1;
    const int row0 = s0 >> 2, seg0 = s0 & 3;
    const int row1 = (s0 + 1) >> 2, seg1 = (s0 + 1) & 3;
    const size_t ga0 = (size_t)(m0 + row0) * H_DIM + (seg0 << 4);
    const size_t ga1 = (size_t)(m0 + row1) * H_DIM + (seg1 << 4);
    const size_t gb0 = (size_t)(v0 + row0) * H_DIM + (seg0 << 4);
    const size_t gb1 = (size_t)(v0 + row1) * H_DIM + (seg1 << 4);
    const int so0 = sw_off(row0, seg0);
    const int so1 = sw_off(row1, seg1);

    // ldmatrix base offsets (kk=0; kk=1 is XOR 32)
    const int r_in = lane & 7;
    int offA[4], offB[2];
    {
        const int hm = (lane >> 3) & 1, hk = lane >> 4;
#pragma unroll
        for (int mi = 0; mi < 4; mi++)
            offA[mi] = P_A + sw_off(wm * 64 + mi * 16 + hm * 8 + r_in, hk);
    }
    {
        const int hkb = (lane >> 3) & 1, hn = lane >> 4;
#pragma unroll
        for (int bi = 0; bi < 2; bi++)
            offB[bi] = P_B + sw_off(wn * 32 + bi * 16 + hn * 8 + r_in, hkb);
    }

    uint32_t c[4][4][2];            // f16x2 accumulators
#pragma unroll
    for (int i = 0; i < 4; i++)
#pragma unroll
        for (int j = 0; j < 4; j++) { c[i][j][0] = 0u; c[i][j][1] = 0u; }

    // prologue: fill NSTAGE stages
#pragma unroll
    for (int st = 0; st < NSTAGE; st++) {
        const uint32_t d = sb + st * STAGE_BYTES;
        const int k0 = st * BK;
        CP16(d + P_A + so0, Aq + ga0 + k0);
        CP16(d + P_A + so1, Aq + ga1 + k0);
        CP16(d + P_B + so0, Bq + gb0 + k0);
        CP16(d + P_B + so1, Bq + gb1 + k0);
        CP_COMMIT();
    }

#pragma unroll 1
    for (int kt = 0; kt < KTILES; kt++) {
        const uint32_t stOff = (kt & (NSTAGE - 1)) * STAGE_BYTES;
        CP_WAIT();
        __syncthreads();

#pragma unroll
        for (int kk = 0; kk < 2; kk++) {        // each kk covers k32 (32B)
            const int kx = kk << 5;
            uint32_t Bh[2][4];
#pragma unroll
            for (int bi = 0; bi < 2; bi++)
                ldsm4(Bh[bi], sb + ((offB[bi] + stOff) ^ kx));
#pragma unroll
            for (int mi = 0; mi < 4; mi++) {
                uint32_t Ah[4];
                ldsm4(Ah, sb + ((offA[mi] + stOff) ^ kx));
#pragma unroll
                for (int nf = 0; nf < 4; nf++)
                    qmma_f16(c[mi][nf], Ah, &Bh[nf >> 1][(nf & 1) * 2]);
            }
        }
        __syncthreads();

        if (kt + NSTAGE < KTILES) {
            const uint32_t d = sb + stOff;
            const int k0 = (kt + NSTAGE) * BK;
            CP16(d + P_A + so0, Aq + ga0 + k0);
            CP16(d + P_A + so1, Aq + ga1 + k0);
            CP16(d + P_B + so0, Bq + gb0 + k0);
            CP16(d + P_B + so1, Bq + gb1 + k0);
        }
        CP_COMMIT();
    }

    // ---- epilogue ----
    const int g = lane >> 2, t = lane & 3;
    float sm8[8], mx16[8][2];
#pragma unroll
    for (int i = 0; i < 8; i++) {
        sm8[i] = 0.f;
        mx16[i][0] = -INFINITY;
        mx16[i][1] = -INFINITY;
    }

#pragma unroll
    for (int mi = 0; mi < 4; mi++) {
#pragma unroll
        for (int nf = 0; nf < 4; nf++) {
            const int col0 = wn * 32 + nf * 8 + 2 * t;
            const float b0v = bias[v0 + col0];
            const float b1v = bias[v0 + col0 + 1];
            const float2 lo = __half22float2(*(const __half2*)&c[mi][nf][0]);
            const float2 hi = __half22float2(*(const __half2*)&c[mi][nf][1]);
            const float x00 = lo.x * INV_SCALE + b0v;
            const float x01 = lo.y * INV_SCALE + b1v;
            const float x10 = hi.x * INV_SCALE + b0v;
            const float x11 = hi.y * INV_SCALE + b1v;
            const int sa = mi * 2, sbI = sa + 1;
            sm8[sa]  += __expf(x00) + __expf(x01);
            sm8[sbI] += __expf(x10) + __expf(x11);
            if (ARG) {
                const int h = nf >> 1;
                mx16[sa][h]  = fmaxf(mx16[sa][h],  fmaxf(x00, x01));
                mx16[sbI][h] = fmaxf(mx16[sbI][h], fmaxf(x10, x11));
            }
        }
    }

    // quad reduce over t
#pragma unroll
    for (int i = 0; i < 8; i++) {
        float s = sm8[i];
        s += __shfl_xor_sync(0xFFFFFFFFu, s, 1);
        s += __shfl_xor_sync(0xFFFFFFFFu, s, 2);
        sm8[i] = s;
        if (ARG) {
#pragma unroll
            for (int h = 0; h < 2; h++) {
                float m = mx16[i][h];
                m = fmaxf(m, __shfl_xor_sync(0xFFFFFFFFu, m, 1));
                m = fmaxf(m, __shfl_xor_sync(0xFFFFFFFFu, m, 2));
                mx16[i][h] = m;
            }
        }
    }

    if (ARG && t == 0) {
        const int gb = blockIdx.y * 8 + wn * 2;
#pragma unroll
        for (int mi = 0; mi < 4; mi++)
#pragma unroll
            for (int hr = 0; hr < 2; hr++) {
                const int rowc = wm * 64 + mi * 16 + hr * 8 + g;
                const int i = mi * 2 + hr;
                g_pmax[(size_t)(m0 + rowc) * NGRP + gb]     = mx16[i][0];
                g_pmax[(size_t)(m0 + rowc) * NGRP + gb + 1] = mx16[i][1];
            }
    }

    // sums: cross-warp combine over 4 quarters via smem
    float* rS = (float*)(smem);           // [3][128]
    __syncthreads();
    if (t == 0 && wn != 0) {
#pragma unroll
        for (int mi = 0; mi < 4; mi++)
#pragma unroll
            for (int hr = 0; hr < 2; hr++) {
                const int rowc = wm * 64 + mi * 16 + hr * 8 + g;
                rS[(wn - 1) * 128 + rowc] = sm8[mi * 2 + hr];
            }
    }
    __syncthreads();
    if (t == 0 && wn == 0) {
#pragma unroll
        for (int mi = 0; mi < 4; mi++)
#pragma unroll
            for (int hr = 0; hr < 2; hr++) {
                const int rowc = wm * 64 + mi * 16 + hr * 8 + g;
                float s = sm8[mi * 2 + hr];
#pragma unroll
                for (int q = 0; q < 3; q++) s += rS[q * 128 + rowc];
                if (ARG) g_psum[(size_t)(m0 + rowc) * 256 + blockIdx.y] = s;
                else     g_rsum[(size_t)(m0 + rowc) * 256 + blockIdx.y] = s;
            }
    }
}

// ============================================================================
// Per token (one warp): approx max, lse, init best, emit candidate groups
// ============================================================================
__global__ void combine_kernel() {
    const int lane = threadIdx.x & 31;
    const int n = blockIdx.x * 8 + (threadIdx.x >> 5);

    float m = -INFINITY;
    for (int g = lane; g < NGRP; g += 32)
        m = fmaxf(m, g_pmax[(size_t)n * NGRP + g]);
#pragma unroll
    for (int off = 16; off >= 1; off >>= 1)
        m = fmaxf(m, __shfl_xor_sync(0xFFFFFFFFu, m, off));

    float s = 0.f;
    for (int sp = lane; sp < NSPLIT; sp += 32)
        s += g_psum[(size_t)n * 256 + sp];
#pragma unroll
    for (int off = 16; off >= 1; off >>= 1)
        s += __shfl_xor_sync(0xFFFFFFFFu, s, off);

    if (lane == 0) {
        g_lse[n] = logf(s);
        g_best[n] = 0ULL;
    }

    const float thr = m - DELTA;
    for (int g = lane; g < NGRP; g += 32) {
        const bool c = g_pmax[(size_t)n * NGRP + g] >= thr;
        const unsigned b = __ballot_sync(0xFFFFFFFFu, c);
        if (b == 0) continue;
        int base = 0;
        if (lane == 0) base = atomicAdd(&g_ccount, __popc(b));
        base = __shfl_sync(0xFFFFFFFFu, base, 0);
        if (c) {
            const int idx = base + __popc(b & ((1u << lane) - 1));
            if (idx < CAND_CAP) g_cand[idx] = ((uint32_t)n << 11) | (uint32_t)g;
        }
    }
}

// ============================================================================
// Exact fp32 recompute of candidate 16-col groups; atomicMax packed result
// ============================================================================
__global__ void fixup_kernel(const float* __restrict__ X,
                             const float* __restrict__ W,
                             const float* __restrict__ bias)
{
    int cnt = g_ccount;
    if (cnt > CAND_CAP) cnt = CAND_CAP;
    const int tid = threadIdx.x;
    const int colo = tid >> 3;     // 0..15
    const int sub  = tid & 7;

    for (int i = blockIdx.x; i < cnt; i += gridDim.x) {
        const uint32_t e = g_cand[i];
        const int n = e >> 11;
        const int g = e & 2047;
        const int vcol = g * 16 + colo;
        const float4* xr = (const float4*)(X + (size_t)n * H_DIM);
        const float4* wr = (const float4*)(W + (size_t)vcol * H_DIM);
        float s = 0.f;
#pragma unroll 8
        for (int j = 0; j < 64; j++) {
            const int idx = j * 8 + sub;
            const float4 a = xr[idx], b = wr[idx];
            s += a.x * b.x + a.y * b.y + a.z * b.z + a.w * b.w;
        }
#pragma unroll
        for (int off = 4; off >= 1; off >>= 1)
            s += __shfl_down_sync(0xFFFFFFFFu, s, off, 8);
        if (sub == 0) {
            const float val = s + bias[vcol];
            const unsigned long long pk =
                ((unsigned long long)fkey(val) << 32) |
                (unsigned long long)(0xFFFFFFFFu - (uint32_t)vcol);
            atomicMax(&g_best[n], pk);
        }
    }
}

// ============================================================================
// Per token: exact ref dot at chosen (needs only g_best; overlaps gemm_r)
// ============================================================================
__global__ void refdot_kernel(const float* __restrict__ refX,
                              const float* __restrict__ refW,
                              const float* __restrict__ refBias)
{
    __shared__ float red[128];
    const int n = blockIdx.x;
    const int tid = threadIdx.x;
    const int chosen = (int)(0xFFFFFFFFu - (uint32_t)(g_best[n] & 0xFFFFFFFFu));

    const float4* xa = (const float4*)(refX + (size_t)n * H_DIM);
    const float4* wa = (const float4*)(refW + (size_t)chosen * H_DIM);
    float s = 0.f;
#pragma unroll
    for (int i = tid; i < H_DIM / 4; i += 128) {
        const float4 a = xa[i], w = wa[i];
        s += a.x * w.x + a.y * w.y + a.z * w.z + a.w * w.w;
    }
    red[tid] = s;
    __syncthreads();
    for (int st = 64; st >= 1; st >>= 1) {
        if (tid < st) red[tid] += red[tid + st];
        __syncthreads();
    }
    if (tid == 0) g_reflogit[n] = red[0] + refBias[chosen];
}

// ============================================================================
// Per token (one warp): ref lse from rsum + KL (tiny, after join)
// ============================================================================
__global__ void kl_kernel() {
    const int lane = threadIdx.x & 31;
    const int n = blockIdx.x * 8 + (threadIdx.x >> 5);

    float rs = 0.f;
    for (int sp = lane; sp < NSPLIT; sp += 32)
        rs += g_rsum[(size_t)n * 256 + sp];
#pragma unroll
    for (int off = 16; off >= 1; off >>= 1)
        rs += __shfl_xor_sync(0xFFFFFFFFu, rs, off);

    if (lane == 0) {
        const unsigned long long p = g_best[n];
        const uint32_t key = (uint32_t)(p >> 32);
        const uint32_t ub = (key & 0x80000000u) ? (key & 0x7FFFFFFFu) : ~key;
        const float best_val = __uint_as_float(ub);
        const float tok_lp = best_val - g_lse[n];
        const float d = (g_reflogit[n] - logf(rs)) - tok_lp;
        g_kl[n] = expm1f(d) - d;
    }
}

// ============================================================================
__global__ void finalize_kernel(const float* __restrict__ mask,
                                const float* __restrict__ rewards,
                                float* __restrict__ out)
{
    __shared__ float sl[256];
    __shared__ float sw[256];
    const int tid = threadIdx.x;
    const double r0 = rewards[0], r1 = rewards[1], r2 = rewards[2], r3 = rewards[3];
    const double mean = (r0 + r1 + r2 + r3) * 0.25;
    const double d0 = r0 - mean, d1 = r1 - mean, d2 = r2 - mean, d3 = r3 - mean;
    const double sd = sqrt((d0 * d0 + d1 * d1 + d2 * d2 + d3 * d3) / 3.0) + 1e-4;
    const float adv[4] = {(float)(d0 / sd), (float)(d1 / sd),
                          (float)(d2 / sd), (float)(d3 / sd)};
    float accL = 0.f, accW = 0.f;
    for (int n = tid; n < N_TOK; n += 256) {
        const float mk = mask[n];
        const int b = n / T_DIM;
        accL += (BETAC * g_kl[n] - adv[b]) * mk;
        accW += mk;
    }
    sl[tid] = accL;
    sw[tid] = accW;
    __syncthreads();
    for (int st = 128; st >= 1; st >>= 1) {
        if (tid < st) { sl[tid] += sl[tid + st]; sw[tid] += sw[tid + st]; }
        __syncthreads();
    }
    if (tid == 0) out[0] = sl[0] / fmaxf(sw[0], 1.0f);
}

// ============================================================================
extern "C" void kernel_launch(void* const* d_in, const int* in_sizes, int n_in,
                              void* d_out, int out_size)
{
    const float* X   = (const float*)d_in[0];
    const float* W   = (const float*)d_in[1];
    const float* msk = (const float*)d_in[2];
    const float* rwd = (const float*)d_in[3];
    const float* bs  = (const float*)d_in[4];
    const float* rX  = (const float*)d_in[5];
    const float* rW  = (const float*)d_in[6];
    const float* rbs = (const float*)d_in[7];
    float* out = (float*)d_out;

    static uint8_t *pWq = nullptr, *prWq, *pXq, *prXq;
    static cudaStream_t s1 = nullptr;
    static cudaEvent_t evF = nullptr, evP = nullptr, evJ = nullptr;
    if (!pWq) {
        cudaGetSymbolAddress((void**)&pWq,  g_Wq);
        cudaGetSymbolAddress((void**)&prWq, g_rWq);
        cudaGetSymbolAddress((void**)&pXq,  g_Xq);
        cudaGetSymbolAddress((void**)&prXq, g_rXq);
        cudaFuncSetAttribute(gemm_fp8<true>,  cudaFuncAttributeMaxDynamicSharedMemorySize, SMEM_BYTES);
        cudaFuncSetAttribute(gemm_fp8<false>, cudaFuncAttributeMaxDynamicSharedMemorySize, SMEM_BYTES);
        cudaStreamCreateWithFlags(&s1, cudaStreamNonBlocking);
        cudaEventCreateWithFlags(&evF, cudaEventDisableTiming);
        cudaEventCreateWithFlags(&evP, cudaEventDisableTiming);
        cudaEventCreateWithFlags(&evJ, cudaEventDisableTiming);
    }

    const int w16 = V_DIM * H_DIM / 16;   // 16000 blocks
    const int x16 = N_TOK * H_DIM / 16;   // 1024 blocks
    dim3 g1(MTILES, NSPLIT);

    // ---- policy pipeline first: splits alone, then gemm_p ----
    reset_kernel<<<1, 1>>>();
    split_fp8<<<w16 / 256, 256>>>((const float4*)W, (uint4*)pWq, w16);
    split_fp8<<<x16 / 256, 256>>>((const float4*)X, (uint4*)pXq, x16);
    cudaEventRecord(evF, 0);              // policy splits done (DRAM free again)
    gemm_fp8<true><<<g1, 256, SMEM_BYTES>>>(pXq, pWq, bs);
    cudaEventRecord(evP, 0);              // gemm_p done

    // ---- ref splits hide under gemm_p (tensor-bound, DRAM idle) ----
    cudaStreamWaitEvent(s1, evF, 0);
    split_fp8<<<w16 / 256, 256, 0, s1>>>((const float4*)rW, (uint4*)prWq, w16);
    split_fp8<<<x16 / 256, 256, 0, s1>>>((const float4*)rX, (uint4*)prXq, x16);

    // ---- gemm_r starts only after gemm_p (no tensor-pipe sharing) ----
    cudaStreamWaitEvent(s1, evP, 0);
    gemm_fp8<false><<<g1, 256, SMEM_BYTES, s1>>>(prXq, prWq, rbs);
    cudaEventRecord(evJ, s1);

    // ---- combine + fixup + refdot hide under gemm_r ----
    combine_kernel<<<N_TOK / 8, 256>>>();
    fixup_kernel<<<2048, 128>>>(X, W, bs);
    refdot_kernel<<<N_TOK, 128>>>(rX, rW, rbs);

    // ---- join: tiny tail ----
    cudaStreamWaitEvent(0, evJ, 0);
    kl_kernel<<<N_TOK / 8, 256>>>();
    finalize_kernel<<<1, 256>>>(msk, rwd, out);
}